// round 12
// baseline (speedup 1.0000x reference)
#include <cuda_runtime.h>
#include <math.h>

// Problem constants: B=2, T=2048, D=1024, H=16, hd=64, M = B*T = 4096
#define MROWS 4096

// ---------------- scratch (device globals; no allocation allowed) ----------
__device__ float g_tpu [2 * 2048];       // time MLP hidden
__device__ float g_tps [2 * 1024];       // time MLP after swiglu
__device__ float g_tp  [2 * 4096];       // shift1|scale1|shift2|scale2
__device__ float g_part[8 * 2 * 4096];   // split-K partials for time MLP
__device__ float g_h   [MROWS * 1024];   // normed/modulated activations
__device__ float g_qkv [MROWS * 3072];   // qkv projections (rope fused)
__device__ float g_att [MROWS * 1024];   // attention output (b,t,h,d)
__device__ float g_x1  [MROWS * 1024];   // x after attention residual
__device__ float g_u   [MROWS * 8192];   // ffn pre-activation
__device__ float g_sw  [MROWS * 4096];   // ffn post-swiglu
__device__ float2 g_ropetab[2048 * 32];  // (cos, sin) per (pos, pair)

// ---------------- PTX helpers ----------------------------------------------
__device__ __forceinline__ unsigned cvt_tf32(float f) {
    unsigned u;
    asm("cvt.rna.tf32.f32 %0, %1;" : "=r"(u) : "f"(f));
    return u;
}

// pack two fp32 into f16x2 (lo -> low half, hi -> high half), RN
__device__ __forceinline__ unsigned pack_f16(float lo, float hi) {
    unsigned d;
    asm("cvt.rn.f16x2.f32 %0, %1, %2;" : "=r"(d) : "f"(hi), "f"(lo));
    return d;
}

__device__ __forceinline__ void mma_tf32(float* c, unsigned a0, unsigned a1,
                                         unsigned a2, unsigned a3,
                                         unsigned b0, unsigned b1) {
    asm volatile(
        "mma.sync.aligned.m16n8k8.row.col.f32.tf32.tf32.f32 "
        "{%0,%1,%2,%3}, {%4,%5,%6,%7}, {%8,%9}, {%0,%1,%2,%3};\n"
        : "+f"(c[0]), "+f"(c[1]), "+f"(c[2]), "+f"(c[3])
        : "r"(a0), "r"(a1), "r"(a2), "r"(a3), "r"(b0), "r"(b1));
}

__device__ __forceinline__ void mma_f16(float* c, unsigned a0, unsigned a1,
                                        unsigned a2, unsigned a3,
                                        unsigned b0, unsigned b1) {
    asm volatile(
        "mma.sync.aligned.m16n8k16.row.col.f32.f16.f16.f32 "
        "{%0,%1,%2,%3}, {%4,%5,%6,%7}, {%8,%9}, {%0,%1,%2,%3};\n"
        : "+f"(c[0]), "+f"(c[1]), "+f"(c[2]), "+f"(c[3])
        : "r"(a0), "r"(a1), "r"(a2), "r"(a3), "r"(b0), "r"(b1));
}

__device__ __forceinline__ void cp16(void* dst, const void* src) {
    unsigned ds = (unsigned)__cvta_generic_to_shared(dst);
    asm volatile("cp.async.cg.shared.global [%0], [%1], 16;\n" :: "r"(ds), "l"(src));
}
__device__ __forceinline__ void cp_commit() {
    asm volatile("cp.async.commit_group;\n");
}
template <int N>
__device__ __forceinline__ void cp_wait() {
    asm volatile("cp.async.wait_group %0;\n" :: "n"(N));
}

// ---------------- time-MLP: split-K partial GEMM + reduce -------------------
__global__ __launch_bounds__(128) void k_tpart(const float* __restrict__ in,
                                               const float* __restrict__ w,
                                               float* __restrict__ part,
                                               int K, int N) {
    int n = blockIdx.x * 128 + threadIdx.x;
    int b = blockIdx.y, s = blockIdx.z;
    const float* xr = in + b * K + s * 128;
    const float* wp = w + (size_t)(s * 128) * N + n;
    float acc = 0.f;
    #pragma unroll 8
    for (int k = 0; k < 128; ++k) acc += xr[k] * wp[(size_t)k * N];
    part[(s * 2 + b) * 4096 + n] = acc;
}

__global__ void k_treduce(const float* __restrict__ part,
                          const float* __restrict__ bias,
                          float* __restrict__ out, int N) {
    int n = blockIdx.x * 256 + threadIdx.x;
    int b = blockIdx.y;
    if (n >= N) return;
    float acc = bias[n];
    #pragma unroll
    for (int s = 0; s < 8; ++s) acc += part[(s * 2 + b) * 4096 + n];
    out[b * N + n] = acc;
}

__global__ void k_tswiglu(const float* __restrict__ u, float* __restrict__ s) {
    int i = blockIdx.x * 256 + threadIdx.x;  // 2048 total
    if (i >= 2048) return;
    int b = i >> 10, j = i & 1023;
    float a = u[b * 2048 + j];
    float g = u[b * 2048 + 1024 + j];
    s[b * 1024 + j] = a * (g / (1.f + expf(-g)));
}

// ---------------- rope cos/sin table ---------------------------------------
__global__ void k_ropetab(float2* __restrict__ tab) {
    int idx = blockIdx.x * 256 + threadIdx.x;   // 65536
    int t = idx >> 5, i = idx & 31;
    float inv = powf(10000.f, -(float)i * (1.f / 32.f));
    float sn, cs;
    sincosf((float)t * inv, &sn, &cs);
    tab[idx] = make_float2(cs, sn);
}

// ---------------- fused RMSNorm + adaLN modulation --------------------------
__global__ __launch_bounds__(256) void k_rmsnorm(const float* __restrict__ x,
                                                 const float* __restrict__ g,
                                                 const float* __restrict__ tp,
                                                 int shift_off, int scale_off,
                                                 float* __restrict__ out) {
    int row = blockIdx.x;          // 0..4095
    int b   = row >> 11;
    const float4* xr = (const float4*)(x + row * 1024);
    float4 v = xr[threadIdx.x];
    float ss = v.x * v.x + v.y * v.y + v.z * v.z + v.w * v.w;
    #pragma unroll
    for (int off = 16; off; off >>= 1) ss += __shfl_xor_sync(0xFFFFFFFFu, ss, off);
    __shared__ float wsum[8];
    __shared__ float stot;
    if ((threadIdx.x & 31) == 0) wsum[threadIdx.x >> 5] = ss;
    __syncthreads();
    if (threadIdx.x == 0) {
        float t = 0.f;
        #pragma unroll
        for (int i = 0; i < 8; ++i) t += wsum[i];
        stot = rsqrtf(t * (1.f / 1024.f) + 1.1920928955078125e-7f);
    }
    __syncthreads();
    float r = stot;
    int j = threadIdx.x * 4;
    const float* gg = g + j;
    const float* sc = tp + b * 4096 + scale_off + j;
    const float* sh = tp + b * 4096 + shift_off + j;
    float4 o;
    o.x = v.x * r * gg[0] * (1.f + sc[0]) + sh[0];
    o.y = v.y * r * gg[1] * (1.f + sc[1]) + sh[1];
    o.z = v.z * r * gg[2] * (1.f + sc[2]) + sh[2];
    o.w = v.w * r * gg[3] * (1.f + sc[3]) + sh[3];
    ((float4*)(out + row * 1024))[threadIdx.x] = o;
}

// ---------------- fp16 tensor-core GEMM, 3-stage cp.async -------------------
// C[M,N] = A[M,K] @ B[K,N] + bias (+residual) (+rope on cols<2048).
// Block 128x128, BK=16, 8 warps 2x4, warp tile 64x32, m16n8k16 f16, fp32 acc.
// Operands staged fp32 via cp.async; converted to fp16 (RN, 10-bit mantissa =
// tf32 precision; range verified in-bounds for this problem) at fragment load.
#define AS(s, m, k) Asm[((s) * 128 + (m)) * 20 + (k)]
#define BS(s, r, n) Bsm[((s) * 16 + (r)) * 132 + (n)]
#define GEMM_SMEM ((3 * 128 * 20 + 3 * 16 * 132) * 4)

template <bool RES, bool ROPE>
__global__ __launch_bounds__(256) void k_tgemm(const float* __restrict__ A,
                                               const float* __restrict__ B,
                                               const float* __restrict__ bias,
                                               const float* __restrict__ res,
                                               const float2* __restrict__ rtab,
                                               float* __restrict__ C,
                                               int Nn, int Kn) {
    extern __shared__ float smemraw[];
    float* Asm = smemraw;                    // [3][128][20]
    float* Bsm = smemraw + 3 * 128 * 20;     // [3][16][132]

    const int tid  = threadIdx.x;
    const int lane = tid & 31;
    const int g    = lane >> 2;
    const int t    = lane & 3;
    const int warp = tid >> 5;
    const int wm   = (warp >> 2) * 64;
    const int wn   = (warp & 3) * 32;

    const int row0 = blockIdx.y * 128;
    const int col0 = blockIdx.x * 128;

    const int arow = tid >> 2;         // 0..63 (+64)
    const int ac4  = tid & 3;
    const int brow = tid >> 5;         // 0..7 (+8)
    const int bc4  = tid & 31;

    const float* Ap0 = A + (size_t)(row0 + arow)      * Kn + ac4 * 4;
    const float* Ap1 = A + (size_t)(row0 + arow + 64) * Kn + ac4 * 4;
    const float* Bp0 = B + (size_t)brow       * Nn + col0 + bc4 * 4;
    const float* Bp1 = B + (size_t)(brow + 8) * Nn + col0 + bc4 * 4;

    float acc[4][4][4];
    #pragma unroll
    for (int mi = 0; mi < 4; ++mi)
        #pragma unroll
        for (int ni = 0; ni < 4; ++ni)
            #pragma unroll
            for (int r = 0; r < 4; ++r) acc[mi][ni][r] = 0.f;

    const int tiles = Kn >> 4;

    #pragma unroll
    for (int s = 0; s < 2; ++s) {
        cp16(&AS(s, arow, ac4 * 4),      Ap0);
        cp16(&AS(s, arow + 64, ac4 * 4), Ap1);
        cp16(&BS(s, brow, bc4 * 4),      Bp0);
        cp16(&BS(s, brow + 8, bc4 * 4),  Bp1);
        cp_commit();
        Ap0 += 16; Ap1 += 16;
        Bp0 += (size_t)16 * Nn; Bp1 += (size_t)16 * Nn;
    }

    for (int i = 0; i < tiles; ++i) {
        const int buf = i % 3;
        cp_wait<1>();
        __syncthreads();
        if (i + 2 < tiles) {
            const int nb = (i + 2) % 3;
            cp16(&AS(nb, arow, ac4 * 4),      Ap0);
            cp16(&AS(nb, arow + 64, ac4 * 4), Ap1);
            cp16(&BS(nb, brow, bc4 * 4),      Bp0);
            cp16(&BS(nb, brow + 8, bc4 * 4),  Bp1);
            Ap0 += 16; Ap1 += 16;
            Bp0 += (size_t)16 * Nn; Bp1 += (size_t)16 * Nn;
        }
        cp_commit();   // always commit (keeps wait<1> semantics on the tail)

        // one k16 step: fragment load + cvt(f16 RN) + 16 mmas
        unsigned af[4][4], bf[4][2];
        #pragma unroll
        for (int mi = 0; mi < 4; ++mi) {
            int m = wm + mi * 16 + g;
            float2 v0 = *(const float2*)&AS(buf, m,     2 * t);
            float2 v1 = *(const float2*)&AS(buf, m + 8, 2 * t);
            float2 v2 = *(const float2*)&AS(buf, m,     8 + 2 * t);
            float2 v3 = *(const float2*)&AS(buf, m + 8, 8 + 2 * t);
            af[mi][0] = pack_f16(v0.x, v0.y);
            af[mi][1] = pack_f16(v1.x, v1.y);
            af[mi][2] = pack_f16(v2.x, v2.y);
            af[mi][3] = pack_f16(v3.x, v3.y);
        }
        #pragma unroll
        for (int ni = 0; ni < 4; ++ni) {
            int n = wn + ni * 8 + g;
            bf[ni][0] = pack_f16(BS(buf, 2 * t,     n), BS(buf, 2 * t + 1, n));
            bf[ni][1] = pack_f16(BS(buf, 8 + 2 * t, n), BS(buf, 9 + 2 * t, n));
        }
        #pragma unroll
        for (int mi = 0; mi < 4; ++mi)
            #pragma unroll
            for (int ni = 0; ni < 4; ++ni)
                mma_f16(acc[mi][ni], af[mi][0], af[mi][1], af[mi][2], af[mi][3],
                        bf[ni][0], bf[ni][1]);
    }

    // epilogue: bias (+residual) (+rope)
    #pragma unroll
    for (int mi = 0; mi < 4; ++mi) {
        int r_top = row0 + wm + mi * 16 + g;
        int r_bot = r_top + 8;
        #pragma unroll
        for (int ni = 0; ni < 4; ++ni) {
            int c = col0 + wn + ni * 8 + 2 * t;   // even column
            float bx = bias[c], by = bias[c + 1];
            float2 w0 = make_float2(acc[mi][ni][0] + bx, acc[mi][ni][1] + by);
            float2 w1 = make_float2(acc[mi][ni][2] + bx, acc[mi][ni][3] + by);
            if (RES) {
                float2 r0 = *(const float2*)(res + (size_t)r_top * Nn + c);
                float2 r1 = *(const float2*)(res + (size_t)r_bot * Nn + c);
                w0.x += r0.x; w0.y += r0.y;
                w1.x += r1.x; w1.y += r1.y;
            }
            if (ROPE && c < 2048) {            // q,k columns get rope
                int i = (c & 63) >> 1;
                float2 cs0 = rtab[(r_top & 2047) * 32 + i];
                float2 cs1 = rtab[(r_bot & 2047) * 32 + i];
                float a0 = w0.x, a1 = w0.y;
                w0.x = a0 * cs0.x - a1 * cs0.y;
                w0.y = a1 * cs0.x + a0 * cs0.y;
                a0 = w1.x; a1 = w1.y;
                w1.x = a0 * cs1.x - a1 * cs1.y;
                w1.y = a1 * cs1.x + a0 * cs1.y;
            }
            *(float2*)(C + (size_t)r_top * Nn + c) = w0;
            *(float2*)(C + (size_t)r_bot * Nn + c) = w1;
        }
    }
}

// ---------------- tensor-core flash attention, cp.async K/V pipeline --------
#define QP_STR 68
#define KS_STR 68
#define VS_STR 72
#define ATTN_SMEM (64 * (QP_STR + 2 * KS_STR + 2 * VS_STR) * 4)

__global__ __launch_bounds__(128) void k_attn(const float* __restrict__ qkv,
                                              float* __restrict__ out) {
    extern __shared__ float sm[];
    float* QP = sm;                                   // 64*68
    float* Ks = sm + 64 * QP_STR;                     // 2 x 64*68
    float* Vs = sm + 64 * (QP_STR + 2 * KS_STR);      // 2 x 64*72

    const int tid  = threadIdx.x;
    const int lane = tid & 31;
    const int g    = lane >> 2;
    const int t    = lane & 3;
    const int warp = tid >> 5;
    const int m0   = warp * 16;

    const int qt = blockIdx.x, bh = blockIdx.y;
    const int b = bh >> 4, h = bh & 15;
    const int base_tok = b * 2048;

    const int ld_row = tid >> 4;
    const int ld_dc  = (tid & 15) << 2;

    #pragma unroll
    for (int rr = 0; rr < 8; ++rr) {
        int row = ld_row + rr * 8;
        int tok = base_tok + row;
        cp16(Ks + row * KS_STR + ld_dc, qkv + (size_t)tok * 3072 + 1024 + h * 64 + ld_dc);
        cp16(Vs + row * VS_STR + ld_dc, qkv + (size_t)tok * 3072 + 2048 + h * 64 + ld_dc);
    }
    cp_commit();

    #pragma unroll
    for (int f = tid; f < 1024; f += 128) {
        int row = f >> 4, dc = (f & 15) << 2;
        int tok = base_tok + qt * 64 + row;
        float4 q4 = *(const float4*)(qkv + (size_t)tok * 3072 + h * 64 + dc);
        uint4 u;
        u.x = cvt_tf32(q4.x * 0.125f); u.y = cvt_tf32(q4.y * 0.125f);
        u.z = cvt_tf32(q4.z * 0.125f); u.w = cvt_tf32(q4.w * 0.125f);
        *(uint4*)(QP + row * QP_STR + dc) = u;
    }
    __syncthreads();

    unsigned qa[8][4];
    #pragma unroll
    for (int ks = 0; ks < 8; ++ks) {
        const unsigned* q0 = (const unsigned*)(QP + (m0 + g) * QP_STR);
        const unsigned* q1 = (const unsigned*)(QP + (m0 + g + 8) * QP_STR);
        qa[ks][0] = q0[ks * 8 + t];
        qa[ks][1] = q1[ks * 8 + t];
        qa[ks][2] = q0[ks * 8 + t + 4];
        qa[ks][3] = q1[ks * 8 + t + 4];
    }

    float o[8][4];
    #pragma unroll
    for (int j = 0; j < 8; ++j)
        #pragma unroll
        for (int r = 0; r < 4; ++r) o[j][r] = 0.f;
    float M1 = -INFINITY, M2 = -INFINITY, L1 = 0.f, L2 = 0.f;

    for (int kt = 0; kt < 32; ++kt) {
        const int buf = kt & 1;
        float* Kb = Ks + buf * 64 * KS_STR;
        float* Vb = Vs + buf * 64 * VS_STR;

        __syncthreads();
        if (kt + 1 < 32) {
            float* Kn = Ks + (buf ^ 1) * 64 * KS_STR;
            float* Vn = Vs + (buf ^ 1) * 64 * VS_STR;
            #pragma unroll
            for (int rr = 0; rr < 8; ++rr) {
                int row = ld_row + rr * 8;
                int tok = base_tok + (kt + 1) * 64 + row;
                cp16(Kn + row * KS_STR + ld_dc, qkv + (size_t)tok * 3072 + 1024 + h * 64 + ld_dc);
                cp16(Vn + row * VS_STR + ld_dc, qkv + (size_t)tok * 3072 + 2048 + h * 64 + ld_dc);
            }
        }
        cp_commit();
        cp_wait<1>();
        __syncthreads();

        float s[8][4];
        #pragma unroll
        for (int j = 0; j < 8; ++j)
            #pragma unroll
            for (int r = 0; r < 4; ++r) s[j][r] = 0.f;

        #pragma unroll
        for (int ks = 0; ks < 8; ++ks) {
            unsigned kb[8][2];
            #pragma unroll
            for (int j = 0; j < 8; ++j) {
                const unsigned* kr = (const unsigned*)(Kb + (j * 8 + g) * KS_STR);
                kb[j][0] = kr[ks * 8 + t]     + 0x1000u;
                kb[j][1] = kr[ks * 8 + t + 4] + 0x1000u;
            }
            #pragma unroll
            for (int j = 0; j < 8; ++j)
                mma_tf32(s[j], qa[ks][0], qa[ks][1], qa[ks][2], qa[ks][3],
                         kb[j][0], kb[j][1]);
        }

        float mx1 = -INFINITY, mx2 = -INFINITY;
        #pragma unroll
        for (int j = 0; j < 8; ++j) {
            mx1 = fmaxf(mx1, fmaxf(s[j][0], s[j][1]));
            mx2 = fmaxf(mx2, fmaxf(s[j][2], s[j][3]));
        }
        mx1 = fmaxf(mx1, __shfl_xor_sync(0xFFFFFFFFu, mx1, 1));
        mx1 = fmaxf(mx1, __shfl_xor_sync(0xFFFFFFFFu, mx1, 2));
        mx2 = fmaxf(mx2, __shfl_xor_sync(0xFFFFFFFFu, mx2, 1));
        mx2 = fmaxf(mx2, __shfl_xor_sync(0xFFFFFFFFu, mx2, 2));
        float mn1 = fmaxf(M1, mx1), mn2 = fmaxf(M2, mx2);
        float cr1 = __expf(M1 - mn1), cr2 = __expf(M2 - mn2);
        float l1 = 0.f, l2 = 0.f;
        #pragma unroll
        for (int j = 0; j < 8; ++j) {
            s[j][0] = __expf(s[j][0] - mn1);
            s[j][1] = __expf(s[j][1] - mn1);
            s[j][2] = __expf(s[j][2] - mn2);
            s[j][3] = __expf(s[j][3] - mn2);
            l1 += s[j][0] + s[j][1];
            l2 += s[j][2] + s[j][3];
        }
        l1 += __shfl_xor_sync(0xFFFFFFFFu, l1, 1);
        l1 += __shfl_xor_sync(0xFFFFFFFFu, l1, 2);
        l2 += __shfl_xor_sync(0xFFFFFFFFu, l2, 1);
        l2 += __shfl_xor_sync(0xFFFFFFFFu, l2, 2);
        L1 = L1 * cr1 + l1;  M1 = mn1;
        L2 = L2 * cr2 + l2;  M2 = mn2;
        #pragma unroll
        for (int j = 0; j < 8; ++j) {
            o[j][0] *= cr1; o[j][1] *= cr1;
            o[j][2] *= cr2; o[j][3] *= cr2;
        }

        #pragma unroll
        for (int j = 0; j < 8; ++j) {
            unsigned* p0 = (unsigned*)(QP + (m0 + g) * QP_STR);
            unsigned* p1 = (unsigned*)(QP + (m0 + g + 8) * QP_STR);
            p0[j * 8 + 2 * t]     = cvt_tf32(s[j][0]);
            p0[j * 8 + 2 * t + 1] = cvt_tf32(s[j][1]);
            p1[j * 8 + 2 * t]     = cvt_tf32(s[j][2]);
            p1[j * 8 + 2 * t + 1] = cvt_tf32(s[j][3]);
        }
        __syncwarp();

        #pragma unroll
        for (int ks = 0; ks < 8; ++ks) {
            const unsigned* p0 = (const unsigned*)(QP + (m0 + g) * QP_STR);
            const unsigned* p1 = (const unsigned*)(QP + (m0 + g + 8) * QP_STR);
            unsigned pa0 = p0[ks * 8 + t];
            unsigned pa1 = p1[ks * 8 + t];
            unsigned pa2 = p0[ks * 8 + t + 4];
            unsigned pa3 = p1[ks * 8 + t + 4];
            #pragma unroll
            for (int j = 0; j < 8; ++j) {
                const unsigned* vr  = (const unsigned*)(Vb + (ks * 8 + t) * VS_STR);
                const unsigned* vr4 = (const unsigned*)(Vb + (ks * 8 + t + 4) * VS_STR);
                unsigned vb0 = vr[j * 8 + g]  + 0x1000u;
                unsigned vb1 = vr4[j * 8 + g] + 0x1000u;
                mma_tf32(o[j], pa0, pa1, pa2, pa3, vb0, vb1);
            }
        }
    }

    float r1 = 1.f / L1, r2 = 1.f / L2;
    int row1 = base_tok + qt * 64 + m0 + g;
    int row2 = row1 + 8;
    #pragma unroll
    for (int j = 0; j < 8; ++j) {
        int c = h * 64 + j * 8 + 2 * t;
        *(float2*)(out + (size_t)row1 * 1024 + c) = make_float2(o[j][0] * r1, o[j][1] * r1);
        *(float2*)(out + (size_t)row2 * 1024 + c) = make_float2(o[j][2] * r2, o[j][3] * r2);
    }
}

// ---------------- SwiGLU for FFN -------------------------------------------
__global__ void k_swiglu(const float* __restrict__ u, float* __restrict__ s) {
    int idx = blockIdx.x * 256 + threadIdx.x;
    int m = idx >> 10, c4 = (idx & 1023) << 2;
    float4 a = *(const float4*)(u + (size_t)m * 8192 + c4);
    float4 g = *(const float4*)(u + (size_t)m * 8192 + 4096 + c4);
    float4 o;
    o.x = a.x * (g.x / (1.f + __expf(-g.x)));
    o.y = a.y * (g.y / (1.f + __expf(-g.y)));
    o.z = a.z * (g.z / (1.f + __expf(-g.z)));
    o.w = a.w * (g.w / (1.f + __expf(-g.w)));
    *(float4*)(s + (size_t)m * 4096 + c4) = o;
}

// ---------------- launcher --------------------------------------------------
extern "C" void kernel_launch(void* const* d_in, const int* in_sizes, int n_in,
                              void* d_out, int out_size) {
    const float* x     = (const float*)d_in[0];
    const float* temb  = (const float*)d_in[1];
    const float* g1    = (const float*)d_in[2];
    const float* g2    = (const float*)d_in[3];
    const float* w_qkv = (const float*)d_in[4];
    const float* b_qkv = (const float*)d_in[5];
    const float* w_ao  = (const float*)d_in[6];
    const float* b_ao  = (const float*)d_in[7];
    const float* w_fc  = (const float*)d_in[8];
    const float* b_fc  = (const float*)d_in[9];
    const float* w_fo  = (const float*)d_in[10];
    const float* b_fo  = (const float*)d_in[11];
    const float* w_t1  = (const float*)d_in[12];
    const float* b_t1  = (const float*)d_in[13];
    const float* w_t2  = (const float*)d_in[14];
    const float* b_t2  = (const float*)d_in[15];
    float* out = (float*)d_out;

    float *tpu, *tps, *tp, *part, *h, *qkv, *att, *x1, *u, *sw;
    float2* rtab;
    cudaGetSymbolAddress((void**)&tpu,  g_tpu);
    cudaGetSymbolAddress((void**)&tps,  g_tps);
    cudaGetSymbolAddress((void**)&tp,   g_tp);
    cudaGetSymbolAddress((void**)&part, g_part);
    cudaGetSymbolAddress((void**)&h,    g_h);
    cudaGetSymbolAddress((void**)&qkv,  g_qkv);
    cudaGetSymbolAddress((void**)&att,  g_att);
    cudaGetSymbolAddress((void**)&x1,   g_x1);
    cudaGetSymbolAddress((void**)&u,    g_u);
    cudaGetSymbolAddress((void**)&sw,   g_sw);
    cudaGetSymbolAddress((void**)&rtab, g_ropetab);

    cudaFuncSetAttribute(k_attn, cudaFuncAttributeMaxDynamicSharedMemorySize, ATTN_SMEM);
    cudaFuncSetAttribute(k_tgemm<false, true>,  cudaFuncAttributeMaxDynamicSharedMemorySize, GEMM_SMEM);
    cudaFuncSetAttribute(k_tgemm<true, false>,  cudaFuncAttributeMaxDynamicSharedMemorySize, GEMM_SMEM);
    cudaFuncSetAttribute(k_tgemm<false, false>, cudaFuncAttributeMaxDynamicSharedMemorySize, GEMM_SMEM);

    // rope table + time-conditioning MLP (split-K, deterministic)
    k_ropetab<<<256, 256>>>(rtab);
    k_tpart<<<dim3(16, 2, 8), 128>>>(temb, w_t1, part, 1024, 2048);
    k_treduce<<<dim3(8, 2), 256>>>(part, b_t1, tpu, 2048);
    k_tswiglu<<<8, 256>>>(tpu, tps);
    k_tpart<<<dim3(32, 2, 8), 128>>>(tps, w_t2, part, 1024, 4096);
    k_treduce<<<dim3(16, 2), 256>>>(part, b_t2, tp, 4096);

    // attention branch
    k_rmsnorm<<<4096, 256>>>(x, g1, tp, 0, 1024, h);
    k_tgemm<false, true><<<dim3(24, 32), 256, GEMM_SMEM>>>(h, w_qkv, b_qkv, nullptr, rtab, qkv, 3072, 1024);
    k_attn<<<dim3(32, 32), 128, ATTN_SMEM>>>(qkv, att);
    k_tgemm<true, false><<<dim3(8, 32), 256, GEMM_SMEM>>>(att, w_ao, b_ao, x, rtab, x1, 1024, 1024);

    // FFN branch
    k_rmsnorm<<<4096, 256>>>(x1, g2, tp, 2048, 3072, h);
    k_tgemm<false, false><<<dim3(64, 32), 256, GEMM_SMEM>>>(h, w_fc, b_fc, nullptr, rtab, u, 8192, 1024);
    k_swiglu<<<16384, 256>>>(u, sw);
    k_tgemm<true, false><<<dim3(8, 32), 256, GEMM_SMEM>>>(sw, w_fo, b_fo, x1, rtab, out, 1024, 4096);
}

// round 13
// speedup vs baseline: 1.0012x; 1.0012x over previous
#include <cuda_runtime.h>
#include <math.h>

// Problem constants: B=2, T=2048, D=1024, H=16, hd=64, M = B*T = 4096
#define MROWS 4096

// ---------------- scratch (device globals; no allocation allowed) ----------
__device__ float g_tpu [2 * 2048];       // time MLP hidden
__device__ float g_tps [2 * 1024];       // time MLP after swiglu
__device__ float g_tp  [2 * 4096];       // shift1|scale1|shift2|scale2
__device__ float g_part[8 * 2 * 4096];   // split-K partials for time MLP
__device__ float g_h   [MROWS * 1024];   // normed/modulated activations
__device__ float g_qkv [MROWS * 3072];   // qkv projections (rope fused)
__device__ float g_att [MROWS * 1024];   // attention output (b,t,h,d)
__device__ float g_x1  [MROWS * 1024];   // x after attention residual
__device__ float g_u   [MROWS * 8192];   // ffn pre-activation
__device__ float g_sw  [MROWS * 4096];   // ffn post-swiglu
__device__ float2 g_ropetab[2048 * 32];  // (cos, sin) per (pos, pair)

// ---------------- PTX helpers ----------------------------------------------
__device__ __forceinline__ unsigned cvt_tf32(float f) {
    unsigned u;
    asm("cvt.rna.tf32.f32 %0, %1;" : "=r"(u) : "f"(f));
    return u;
}

// pack two fp32 into f16x2 (lo -> low half, hi -> high half), RN
__device__ __forceinline__ unsigned pack_f16(float lo, float hi) {
    unsigned d;
    asm("cvt.rn.f16x2.f32 %0, %1, %2;" : "=r"(d) : "f"(hi), "f"(lo));
    return d;
}

__device__ __forceinline__ void mma_tf32(float* c, unsigned a0, unsigned a1,
                                         unsigned a2, unsigned a3,
                                         unsigned b0, unsigned b1) {
    asm volatile(
        "mma.sync.aligned.m16n8k8.row.col.f32.tf32.tf32.f32 "
        "{%0,%1,%2,%3}, {%4,%5,%6,%7}, {%8,%9}, {%0,%1,%2,%3};\n"
        : "+f"(c[0]), "+f"(c[1]), "+f"(c[2]), "+f"(c[3])
        : "r"(a0), "r"(a1), "r"(a2), "r"(a3), "r"(b0), "r"(b1));
}

__device__ __forceinline__ void mma_f16(float* c, unsigned a0, unsigned a1,
                                        unsigned a2, unsigned a3,
                                        unsigned b0, unsigned b1) {
    asm volatile(
        "mma.sync.aligned.m16n8k16.row.col.f32.f16.f16.f32 "
        "{%0,%1,%2,%3}, {%4,%5,%6,%7}, {%8,%9}, {%0,%1,%2,%3};\n"
        : "+f"(c[0]), "+f"(c[1]), "+f"(c[2]), "+f"(c[3])
        : "r"(a0), "r"(a1), "r"(a2), "r"(a3), "r"(b0), "r"(b1));
}

__device__ __forceinline__ void cp16(void* dst, const void* src) {
    unsigned ds = (unsigned)__cvta_generic_to_shared(dst);
    asm volatile("cp.async.cg.shared.global [%0], [%1], 16;\n" :: "r"(ds), "l"(src));
}
__device__ __forceinline__ void cp_commit() {
    asm volatile("cp.async.commit_group;\n");
}
template <int N>
__device__ __forceinline__ void cp_wait() {
    asm volatile("cp.async.wait_group %0;\n" :: "n"(N));
}

// ---------------- time-MLP: split-K partial GEMM + reduce -------------------
__global__ __launch_bounds__(128) void k_tpart(const float* __restrict__ in,
                                               const float* __restrict__ w,
                                               float* __restrict__ part,
                                               int K, int N) {
    int n = blockIdx.x * 128 + threadIdx.x;
    int b = blockIdx.y, s = blockIdx.z;
    const float* xr = in + b * K + s * 128;
    const float* wp = w + (size_t)(s * 128) * N + n;
    float acc = 0.f;
    #pragma unroll 8
    for (int k = 0; k < 128; ++k) acc += xr[k] * wp[(size_t)k * N];
    part[(s * 2 + b) * 4096 + n] = acc;
}

__global__ void k_treduce(const float* __restrict__ part,
                          const float* __restrict__ bias,
                          float* __restrict__ out, int N) {
    int n = blockIdx.x * 256 + threadIdx.x;
    int b = blockIdx.y;
    if (n >= N) return;
    float acc = bias[n];
    #pragma unroll
    for (int s = 0; s < 8; ++s) acc += part[(s * 2 + b) * 4096 + n];
    out[b * N + n] = acc;
}

__global__ void k_tswiglu(const float* __restrict__ u, float* __restrict__ s) {
    int i = blockIdx.x * 256 + threadIdx.x;  // 2048 total
    if (i >= 2048) return;
    int b = i >> 10, j = i & 1023;
    float a = u[b * 2048 + j];
    float g = u[b * 2048 + 1024 + j];
    s[b * 1024 + j] = a * (g / (1.f + expf(-g)));
}

// ---------------- rope cos/sin table ---------------------------------------
__global__ void k_ropetab(float2* __restrict__ tab) {
    int idx = blockIdx.x * 256 + threadIdx.x;   // 65536
    int t = idx >> 5, i = idx & 31;
    float inv = powf(10000.f, -(float)i * (1.f / 32.f));
    float sn, cs;
    sincosf((float)t * inv, &sn, &cs);
    tab[idx] = make_float2(cs, sn);
}

// ---------------- fused RMSNorm + adaLN modulation --------------------------
__global__ __launch_bounds__(256) void k_rmsnorm(const float* __restrict__ x,
                                                 const float* __restrict__ g,
                                                 const float* __restrict__ tp,
                                                 int shift_off, int scale_off,
                                                 float* __restrict__ out) {
    int row = blockIdx.x;          // 0..4095
    int b   = row >> 11;
    const float4* xr = (const float4*)(x + row * 1024);
    float4 v = xr[threadIdx.x];
    float ss = v.x * v.x + v.y * v.y + v.z * v.z + v.w * v.w;
    #pragma unroll
    for (int off = 16; off; off >>= 1) ss += __shfl_xor_sync(0xFFFFFFFFu, ss, off);
    __shared__ float wsum[8];
    __shared__ float stot;
    if ((threadIdx.x & 31) == 0) wsum[threadIdx.x >> 5] = ss;
    __syncthreads();
    if (threadIdx.x == 0) {
        float t = 0.f;
        #pragma unroll
        for (int i = 0; i < 8; ++i) t += wsum[i];
        stot = rsqrtf(t * (1.f / 1024.f) + 1.1920928955078125e-7f);
    }
    __syncthreads();
    float r = stot;
    int j = threadIdx.x * 4;
    const float* gg = g + j;
    const float* sc = tp + b * 4096 + scale_off + j;
    const float* sh = tp + b * 4096 + shift_off + j;
    float4 o;
    o.x = v.x * r * gg[0] * (1.f + sc[0]) + sh[0];
    o.y = v.y * r * gg[1] * (1.f + sc[1]) + sh[1];
    o.z = v.z * r * gg[2] * (1.f + sc[2]) + sh[2];
    o.w = v.w * r * gg[3] * (1.f + sc[3]) + sh[3];
    ((float4*)(out + row * 1024))[threadIdx.x] = o;
}

// ---------------- fp16 tensor-core GEMM, 3-stage cp.async -------------------
// C[M,N] = A[M,K] @ B[K,N] + bias (+residual) (+rope on cols<2048).
// Block 128x128, BK=16, 8 warps 2x4, warp tile 64x32, m16n8k16 f16, fp32 acc.
// Operands staged fp32 via cp.async; converted to fp16 (RN, 10-bit mantissa =
// tf32 precision; range verified in-bounds for this problem) at fragment load.
#define AS(s, m, k) Asm[((s) * 128 + (m)) * 20 + (k)]
#define BS(s, r, n) Bsm[((s) * 16 + (r)) * 132 + (n)]
#define GEMM_SMEM ((3 * 128 * 20 + 3 * 16 * 132) * 4)

template <bool RES, bool ROPE>
__global__ __launch_bounds__(256) void k_tgemm(const float* __restrict__ A,
                                               const float* __restrict__ B,
                                               const float* __restrict__ bias,
                                               const float* __restrict__ res,
                                               const float2* __restrict__ rtab,
                                               float* __restrict__ C,
                                               int Nn, int Kn) {
    extern __shared__ float smemraw[];
    float* Asm = smemraw;                    // [3][128][20]
    float* Bsm = smemraw + 3 * 128 * 20;     // [3][16][132]

    const int tid  = threadIdx.x;
    const int lane = tid & 31;
    const int g    = lane >> 2;
    const int t    = lane & 3;
    const int warp = tid >> 5;
    const int wm   = (warp >> 2) * 64;
    const int wn   = (warp & 3) * 32;

    const int row0 = blockIdx.y * 128;
    const int col0 = blockIdx.x * 128;

    const int arow = tid >> 2;         // 0..63 (+64)
    const int ac4  = tid & 3;
    const int brow = tid >> 5;         // 0..7 (+8)
    const int bc4  = tid & 31;

    const float* Ap0 = A + (size_t)(row0 + arow)      * Kn + ac4 * 4;
    const float* Ap1 = A + (size_t)(row0 + arow + 64) * Kn + ac4 * 4;
    const float* Bp0 = B + (size_t)brow       * Nn + col0 + bc4 * 4;
    const float* Bp1 = B + (size_t)(brow + 8) * Nn + col0 + bc4 * 4;

    float acc[4][4][4];
    #pragma unroll
    for (int mi = 0; mi < 4; ++mi)
        #pragma unroll
        for (int ni = 0; ni < 4; ++ni)
            #pragma unroll
            for (int r = 0; r < 4; ++r) acc[mi][ni][r] = 0.f;

    const int tiles = Kn >> 4;

    #pragma unroll
    for (int s = 0; s < 2; ++s) {
        cp16(&AS(s, arow, ac4 * 4),      Ap0);
        cp16(&AS(s, arow + 64, ac4 * 4), Ap1);
        cp16(&BS(s, brow, bc4 * 4),      Bp0);
        cp16(&BS(s, brow + 8, bc4 * 4),  Bp1);
        cp_commit();
        Ap0 += 16; Ap1 += 16;
        Bp0 += (size_t)16 * Nn; Bp1 += (size_t)16 * Nn;
    }

    for (int i = 0; i < tiles; ++i) {
        const int buf = i % 3;
        cp_wait<1>();
        __syncthreads();
        if (i + 2 < tiles) {
            const int nb = (i + 2) % 3;
            cp16(&AS(nb, arow, ac4 * 4),      Ap0);
            cp16(&AS(nb, arow + 64, ac4 * 4), Ap1);
            cp16(&BS(nb, brow, bc4 * 4),      Bp0);
            cp16(&BS(nb, brow + 8, bc4 * 4),  Bp1);
            Ap0 += 16; Ap1 += 16;
            Bp0 += (size_t)16 * Nn; Bp1 += (size_t)16 * Nn;
        }
        cp_commit();   // always commit (keeps wait<1> semantics on the tail)

        // one k16 step: fragment load + cvt(f16 RN) + 16 mmas
        unsigned af[4][4], bf[4][2];
        #pragma unroll
        for (int mi = 0; mi < 4; ++mi) {
            int m = wm + mi * 16 + g;
            float2 v0 = *(const float2*)&AS(buf, m,     2 * t);
            float2 v1 = *(const float2*)&AS(buf, m + 8, 2 * t);
            float2 v2 = *(const float2*)&AS(buf, m,     8 + 2 * t);
            float2 v3 = *(const float2*)&AS(buf, m + 8, 8 + 2 * t);
            af[mi][0] = pack_f16(v0.x, v0.y);
            af[mi][1] = pack_f16(v1.x, v1.y);
            af[mi][2] = pack_f16(v2.x, v2.y);
            af[mi][3] = pack_f16(v3.x, v3.y);
        }
        #pragma unroll
        for (int ni = 0; ni < 4; ++ni) {
            int n = wn + ni * 8 + g;
            bf[ni][0] = pack_f16(BS(buf, 2 * t,     n), BS(buf, 2 * t + 1, n));
            bf[ni][1] = pack_f16(BS(buf, 8 + 2 * t, n), BS(buf, 9 + 2 * t, n));
        }
        #pragma unroll
        for (int mi = 0; mi < 4; ++mi)
            #pragma unroll
            for (int ni = 0; ni < 4; ++ni)
                mma_f16(acc[mi][ni], af[mi][0], af[mi][1], af[mi][2], af[mi][3],
                        bf[ni][0], bf[ni][1]);
    }

    // epilogue: bias (+residual) (+rope)
    #pragma unroll
    for (int mi = 0; mi < 4; ++mi) {
        int r_top = row0 + wm + mi * 16 + g;
        int r_bot = r_top + 8;
        #pragma unroll
        for (int ni = 0; ni < 4; ++ni) {
            int c = col0 + wn + ni * 8 + 2 * t;   // even column
            float bx = bias[c], by = bias[c + 1];
            float2 w0 = make_float2(acc[mi][ni][0] + bx, acc[mi][ni][1] + by);
            float2 w1 = make_float2(acc[mi][ni][2] + bx, acc[mi][ni][3] + by);
            if (RES) {
                float2 r0 = *(const float2*)(res + (size_t)r_top * Nn + c);
                float2 r1 = *(const float2*)(res + (size_t)r_bot * Nn + c);
                w0.x += r0.x; w0.y += r0.y;
                w1.x += r1.x; w1.y += r1.y;
            }
            if (ROPE && c < 2048) {            // q,k columns get rope
                int i = (c & 63) >> 1;
                float2 cs0 = rtab[(r_top & 2047) * 32 + i];
                float2 cs1 = rtab[(r_bot & 2047) * 32 + i];
                float a0 = w0.x, a1 = w0.y;
                w0.x = a0 * cs0.x - a1 * cs0.y;
                w0.y = a1 * cs0.x + a0 * cs0.y;
                a0 = w1.x; a1 = w1.y;
                w1.x = a0 * cs1.x - a1 * cs1.y;
                w1.y = a1 * cs1.x + a0 * cs1.y;
            }
            *(float2*)(C + (size_t)r_top * Nn + c) = w0;
            *(float2*)(C + (size_t)r_bot * Nn + c) = w1;
        }
    }
}

// ---------------- tensor-core flash attention, cp.async K/V pipeline --------
#define QP_STR 68
#define KS_STR 68
#define VS_STR 72
#define ATTN_SMEM (64 * (QP_STR + 2 * KS_STR + 2 * VS_STR) * 4)

__global__ __launch_bounds__(128) void k_attn(const float* __restrict__ qkv,
                                              float* __restrict__ out) {
    extern __shared__ float sm[];
    float* QP = sm;                                   // 64*68
    float* Ks = sm + 64 * QP_STR;                     // 2 x 64*68
    float* Vs = sm + 64 * (QP_STR + 2 * KS_STR);      // 2 x 64*72

    const int tid  = threadIdx.x;
    const int lane = tid & 31;
    const int g    = lane >> 2;
    const int t    = lane & 3;
    const int warp = tid >> 5;
    const int m0   = warp * 16;

    const int qt = blockIdx.x, bh = blockIdx.y;
    const int b = bh >> 4, h = bh & 15;
    const int base_tok = b * 2048;

    const int ld_row = tid >> 4;
    const int ld_dc  = (tid & 15) << 2;

    #pragma unroll
    for (int rr = 0; rr < 8; ++rr) {
        int row = ld_row + rr * 8;
        int tok = base_tok + row;
        cp16(Ks + row * KS_STR + ld_dc, qkv + (size_t)tok * 3072 + 1024 + h * 64 + ld_dc);
        cp16(Vs + row * VS_STR + ld_dc, qkv + (size_t)tok * 3072 + 2048 + h * 64 + ld_dc);
    }
    cp_commit();

    #pragma unroll
    for (int f = tid; f < 1024; f += 128) {
        int row = f >> 4, dc = (f & 15) << 2;
        int tok = base_tok + qt * 64 + row;
        float4 q4 = *(const float4*)(qkv + (size_t)tok * 3072 + h * 64 + dc);
        uint4 u;
        u.x = cvt_tf32(q4.x * 0.125f); u.y = cvt_tf32(q4.y * 0.125f);
        u.z = cvt_tf32(q4.z * 0.125f); u.w = cvt_tf32(q4.w * 0.125f);
        *(uint4*)(QP + row * QP_STR + dc) = u;
    }
    __syncthreads();

    unsigned qa[8][4];
    #pragma unroll
    for (int ks = 0; ks < 8; ++ks) {
        const unsigned* q0 = (const unsigned*)(QP + (m0 + g) * QP_STR);
        const unsigned* q1 = (const unsigned*)(QP + (m0 + g + 8) * QP_STR);
        qa[ks][0] = q0[ks * 8 + t];
        qa[ks][1] = q1[ks * 8 + t];
        qa[ks][2] = q0[ks * 8 + t + 4];
        qa[ks][3] = q1[ks * 8 + t + 4];
    }

    float o[8][4];
    #pragma unroll
    for (int j = 0; j < 8; ++j)
        #pragma unroll
        for (int r = 0; r < 4; ++r) o[j][r] = 0.f;
    float M1 = -INFINITY, M2 = -INFINITY, L1 = 0.f, L2 = 0.f;

    for (int kt = 0; kt < 32; ++kt) {
        const int buf = kt & 1;
        float* Kb = Ks + buf * 64 * KS_STR;
        float* Vb = Vs + buf * 64 * VS_STR;

        __syncthreads();
        if (kt + 1 < 32) {
            float* Kn = Ks + (buf ^ 1) * 64 * KS_STR;
            float* Vn = Vs + (buf ^ 1) * 64 * VS_STR;
            #pragma unroll
            for (int rr = 0; rr < 8; ++rr) {
                int row = ld_row + rr * 8;
                int tok = base_tok + (kt + 1) * 64 + row;
                cp16(Kn + row * KS_STR + ld_dc, qkv + (size_t)tok * 3072 + 1024 + h * 64 + ld_dc);
                cp16(Vn + row * VS_STR + ld_dc, qkv + (size_t)tok * 3072 + 2048 + h * 64 + ld_dc);
            }
        }
        cp_commit();
        cp_wait<1>();
        __syncthreads();

        float s[8][4];
        #pragma unroll
        for (int j = 0; j < 8; ++j)
            #pragma unroll
            for (int r = 0; r < 4; ++r) s[j][r] = 0.f;

        #pragma unroll
        for (int ks = 0; ks < 8; ++ks) {
            unsigned kb[8][2];
            #pragma unroll
            for (int j = 0; j < 8; ++j) {
                const unsigned* kr = (const unsigned*)(Kb + (j * 8 + g) * KS_STR);
                kb[j][0] = kr[ks * 8 + t]     + 0x1000u;
                kb[j][1] = kr[ks * 8 + t + 4] + 0x1000u;
            }
            #pragma unroll
            for (int j = 0; j < 8; ++j)
                mma_tf32(s[j], qa[ks][0], qa[ks][1], qa[ks][2], qa[ks][3],
                         kb[j][0], kb[j][1]);
        }

        float mx1 = -INFINITY, mx2 = -INFINITY;
        #pragma unroll
        for (int j = 0; j < 8; ++j) {
            mx1 = fmaxf(mx1, fmaxf(s[j][0], s[j][1]));
            mx2 = fmaxf(mx2, fmaxf(s[j][2], s[j][3]));
        }
        mx1 = fmaxf(mx1, __shfl_xor_sync(0xFFFFFFFFu, mx1, 1));
        mx1 = fmaxf(mx1, __shfl_xor_sync(0xFFFFFFFFu, mx1, 2));
        mx2 = fmaxf(mx2, __shfl_xor_sync(0xFFFFFFFFu, mx2, 1));
        mx2 = fmaxf(mx2, __shfl_xor_sync(0xFFFFFFFFu, mx2, 2));
        float mn1 = fmaxf(M1, mx1), mn2 = fmaxf(M2, mx2);
        float cr1 = __expf(M1 - mn1), cr2 = __expf(M2 - mn2);
        float l1 = 0.f, l2 = 0.f;
        #pragma unroll
        for (int j = 0; j < 8; ++j) {
            s[j][0] = __expf(s[j][0] - mn1);
            s[j][1] = __expf(s[j][1] - mn1);
            s[j][2] = __expf(s[j][2] - mn2);
            s[j][3] = __expf(s[j][3] - mn2);
            l1 += s[j][0] + s[j][1];
            l2 += s[j][2] + s[j][3];
        }
        l1 += __shfl_xor_sync(0xFFFFFFFFu, l1, 1);
        l1 += __shfl_xor_sync(0xFFFFFFFFu, l1, 2);
        l2 += __shfl_xor_sync(0xFFFFFFFFu, l2, 1);
        l2 += __shfl_xor_sync(0xFFFFFFFFu, l2, 2);
        L1 = L1 * cr1 + l1;  M1 = mn1;
        L2 = L2 * cr2 + l2;  M2 = mn2;
        #pragma unroll
        for (int j = 0; j < 8; ++j) {
            o[j][0] *= cr1; o[j][1] *= cr1;
            o[j][2] *= cr2; o[j][3] *= cr2;
        }

        #pragma unroll
        for (int j = 0; j < 8; ++j) {
            unsigned* p0 = (unsigned*)(QP + (m0 + g) * QP_STR);
            unsigned* p1 = (unsigned*)(QP + (m0 + g + 8) * QP_STR);
            p0[j * 8 + 2 * t]     = cvt_tf32(s[j][0]);
            p0[j * 8 + 2 * t + 1] = cvt_tf32(s[j][1]);
            p1[j * 8 + 2 * t]     = cvt_tf32(s[j][2]);
            p1[j * 8 + 2 * t + 1] = cvt_tf32(s[j][3]);
        }
        __syncwarp();

        #pragma unroll
        for (int ks = 0; ks < 8; ++ks) {
            const unsigned* p0 = (const unsigned*)(QP + (m0 + g) * QP_STR);
            const unsigned* p1 = (const unsigned*)(QP + (m0 + g + 8) * QP_STR);
            unsigned pa0 = p0[ks * 8 + t];
            unsigned pa1 = p1[ks * 8 + t];
            unsigned pa2 = p0[ks * 8 + t + 4];
            unsigned pa3 = p1[ks * 8 + t + 4];
            #pragma unroll
            for (int j = 0; j < 8; ++j) {
                const unsigned* vr  = (const unsigned*)(Vb + (ks * 8 + t) * VS_STR);
                const unsigned* vr4 = (const unsigned*)(Vb + (ks * 8 + t + 4) * VS_STR);
                unsigned vb0 = vr[j * 8 + g]  + 0x1000u;
                unsigned vb1 = vr4[j * 8 + g] + 0x1000u;
                mma_tf32(o[j], pa0, pa1, pa2, pa3, vb0, vb1);
            }
        }
    }

    float r1 = 1.f / L1, r2 = 1.f / L2;
    int row1 = base_tok + qt * 64 + m0 + g;
    int row2 = row1 + 8;
    #pragma unroll
    for (int j = 0; j < 8; ++j) {
        int c = h * 64 + j * 8 + 2 * t;
        *(float2*)(out + (size_t)row1 * 1024 + c) = make_float2(o[j][0] * r1, o[j][1] * r1);
        *(float2*)(out + (size_t)row2 * 1024 + c) = make_float2(o[j][2] * r2, o[j][3] * r2);
    }
}

// ---------------- SwiGLU for FFN -------------------------------------------
__global__ void k_swiglu(const float* __restrict__ u, float* __restrict__ s) {
    int idx = blockIdx.x * 256 + threadIdx.x;
    int m = idx >> 10, c4 = (idx & 1023) << 2;
    float4 a = *(const float4*)(u + (size_t)m * 8192 + c4);
    float4 g = *(const float4*)(u + (size_t)m * 8192 + 4096 + c4);
    float4 o;
    o.x = a.x * (g.x / (1.f + __expf(-g.x)));
    o.y = a.y * (g.y / (1.f + __expf(-g.y)));
    o.z = a.z * (g.z / (1.f + __expf(-g.z)));
    o.w = a.w * (g.w / (1.f + __expf(-g.w)));
    *(float4*)(s + (size_t)m * 4096 + c4) = o;
}

// ---------------- launcher --------------------------------------------------
extern "C" void kernel_launch(void* const* d_in, const int* in_sizes, int n_in,
                              void* d_out, int out_size) {
    const float* x     = (const float*)d_in[0];
    const float* temb  = (const float*)d_in[1];
    const float* g1    = (const float*)d_in[2];
    const float* g2    = (const float*)d_in[3];
    const float* w_qkv = (const float*)d_in[4];
    const float* b_qkv = (const float*)d_in[5];
    const float* w_ao  = (const float*)d_in[6];
    const float* b_ao  = (const float*)d_in[7];
    const float* w_fc  = (const float*)d_in[8];
    const float* b_fc  = (const float*)d_in[9];
    const float* w_fo  = (const float*)d_in[10];
    const float* b_fo  = (const float*)d_in[11];
    const float* w_t1  = (const float*)d_in[12];
    const float* b_t1  = (const float*)d_in[13];
    const float* w_t2  = (const float*)d_in[14];
    const float* b_t2  = (const float*)d_in[15];
    float* out = (float*)d_out;

    float *tpu, *tps, *tp, *part, *h, *qkv, *att, *x1, *u, *sw;
    float2* rtab;
    cudaGetSymbolAddress((void**)&tpu,  g_tpu);
    cudaGetSymbolAddress((void**)&tps,  g_tps);
    cudaGetSymbolAddress((void**)&tp,   g_tp);
    cudaGetSymbolAddress((void**)&part, g_part);
    cudaGetSymbolAddress((void**)&h,    g_h);
    cudaGetSymbolAddress((void**)&qkv,  g_qkv);
    cudaGetSymbolAddress((void**)&att,  g_att);
    cudaGetSymbolAddress((void**)&x1,   g_x1);
    cudaGetSymbolAddress((void**)&u,    g_u);
    cudaGetSymbolAddress((void**)&sw,   g_sw);
    cudaGetSymbolAddress((void**)&rtab, g_ropetab);

    cudaFuncSetAttribute(k_attn, cudaFuncAttributeMaxDynamicSharedMemorySize, ATTN_SMEM);
    cudaFuncSetAttribute(k_tgemm<false, true>,  cudaFuncAttributeMaxDynamicSharedMemorySize, GEMM_SMEM);
    cudaFuncSetAttribute(k_tgemm<true, false>,  cudaFuncAttributeMaxDynamicSharedMemorySize, GEMM_SMEM);
    cudaFuncSetAttribute(k_tgemm<false, false>, cudaFuncAttributeMaxDynamicSharedMemorySize, GEMM_SMEM);

    // rope table + time-conditioning MLP (split-K, deterministic)
    k_ropetab<<<256, 256>>>(rtab);
    k_tpart<<<dim3(16, 2, 8), 128>>>(temb, w_t1, part, 1024, 2048);
    k_treduce<<<dim3(8, 2), 256>>>(part, b_t1, tpu, 2048);
    k_tswiglu<<<8, 256>>>(tpu, tps);
    k_tpart<<<dim3(32, 2, 8), 128>>>(tps, w_t2, part, 1024, 4096);
    k_treduce<<<dim3(16, 2), 256>>>(part, b_t2, tp, 4096);

    // attention branch
    k_rmsnorm<<<4096, 256>>>(x, g1, tp, 0, 1024, h);
    k_tgemm<false, true><<<dim3(24, 32), 256, GEMM_SMEM>>>(h, w_qkv, b_qkv, nullptr, rtab, qkv, 3072, 1024);
    k_attn<<<dim3(32, 32), 128, ATTN_SMEM>>>(qkv, att);
    k_tgemm<true, false><<<dim3(8, 32), 256, GEMM_SMEM>>>(att, w_ao, b_ao, x, rtab, x1, 1024, 1024);

    // FFN branch
    k_rmsnorm<<<4096, 256>>>(x1, g2, tp, 2048, 3072, h);
    k_tgemm<false, false><<<dim3(64, 32), 256, GEMM_SMEM>>>(h, w_fc, b_fc, nullptr, rtab, u, 8192, 1024);
    k_swiglu<<<16384, 256>>>(u, sw);
    k_tgemm<true, false><<<dim3(8, 32), 256, GEMM_SMEM>>>(sw, w_fo, b_fo, x1, rtab, out, 1024, 4096);
}

// round 15
// speedup vs baseline: 1.1920x; 1.1905x over previous
#include <cuda_runtime.h>
#include <math.h>

// Problem constants: B=2, T=2048, D=1024, H=16, hd=64, M = B*T = 4096
#define MROWS 4096

// ---------------- scratch (device globals; no allocation allowed) ----------
__device__ float g_tpu [2 * 2048];       // time MLP hidden
__device__ float g_tps [2 * 1024];       // time MLP after swiglu
__device__ float g_tp  [2 * 4096];       // shift1|scale1|shift2|scale2
__device__ float g_part[8 * 2 * 4096];   // split-K partials for time MLP
__device__ float g_h   [MROWS * 1024];   // normed/modulated activations
__device__ float g_qkv [MROWS * 3072];   // qkv projections (rope fused)
__device__ float g_att [MROWS * 1024];   // attention output (b,t,h,d)
__device__ float g_x1  [MROWS * 1024];   // x after attention residual
__device__ float g_u   [MROWS * 8192];   // ffn pre-activation
__device__ float g_sw  [MROWS * 4096];   // ffn post-swiglu
__device__ float2 g_ropetab[2048 * 32];  // (cos, sin) per (pos, pair)

// ---------------- PTX helpers ----------------------------------------------
__device__ __forceinline__ unsigned cvt_tf32(float f) {
    unsigned u;
    asm("cvt.rna.tf32.f32 %0, %1;" : "=r"(u) : "f"(f));
    return u;
}

// pack two fp32 into f16x2 (lo -> low half, hi -> high half), RN
__device__ __forceinline__ unsigned pack_f16(float lo, float hi) {
    unsigned d;
    asm("cvt.rn.f16x2.f32 %0, %1, %2;" : "=r"(d) : "f"(hi), "f"(lo));
    return d;
}

__device__ __forceinline__ void mma_tf32(float* c, unsigned a0, unsigned a1,
                                         unsigned a2, unsigned a3,
                                         unsigned b0, unsigned b1) {
    asm volatile(
        "mma.sync.aligned.m16n8k8.row.col.f32.tf32.tf32.f32 "
        "{%0,%1,%2,%3}, {%4,%5,%6,%7}, {%8,%9}, {%0,%1,%2,%3};\n"
        : "+f"(c[0]), "+f"(c[1]), "+f"(c[2]), "+f"(c[3])
        : "r"(a0), "r"(a1), "r"(a2), "r"(a3), "r"(b0), "r"(b1));
}

__device__ __forceinline__ void mma_f16(float* c, unsigned a0, unsigned a1,
                                        unsigned a2, unsigned a3,
                                        unsigned b0, unsigned b1) {
    asm volatile(
        "mma.sync.aligned.m16n8k16.row.col.f32.f16.f16.f32 "
        "{%0,%1,%2,%3}, {%4,%5,%6,%7}, {%8,%9}, {%0,%1,%2,%3};\n"
        : "+f"(c[0]), "+f"(c[1]), "+f"(c[2]), "+f"(c[3])
        : "r"(a0), "r"(a1), "r"(a2), "r"(a3), "r"(b0), "r"(b1));
}

__device__ __forceinline__ void ldsm4(unsigned& r0, unsigned& r1,
                                      unsigned& r2, unsigned& r3, unsigned addr) {
    asm volatile("ldmatrix.sync.aligned.m8n8.x4.shared.b16 {%0,%1,%2,%3}, [%4];"
                 : "=r"(r0), "=r"(r1), "=r"(r2), "=r"(r3) : "r"(addr));
}

__device__ __forceinline__ void ldsm4t(unsigned& r0, unsigned& r1,
                                       unsigned& r2, unsigned& r3, unsigned addr) {
    asm volatile("ldmatrix.sync.aligned.m8n8.x4.trans.shared.b16 {%0,%1,%2,%3}, [%4];"
                 : "=r"(r0), "=r"(r1), "=r"(r2), "=r"(r3) : "r"(addr));
}

__device__ __forceinline__ void cp16(void* dst, const void* src) {
    unsigned ds = (unsigned)__cvta_generic_to_shared(dst);
    asm volatile("cp.async.cg.shared.global [%0], [%1], 16;\n" :: "r"(ds), "l"(src));
}
__device__ __forceinline__ void cp_commit() {
    asm volatile("cp.async.commit_group;\n");
}
template <int N>
__device__ __forceinline__ void cp_wait() {
    asm volatile("cp.async.wait_group %0;\n" :: "n"(N));
}

// ---------------- time-MLP: split-K partial GEMM + reduce -------------------
__global__ __launch_bounds__(128) void k_tpart(const float* __restrict__ in,
                                               const float* __restrict__ w,
                                               float* __restrict__ part,
                                               int K, int N) {
    int n = blockIdx.x * 128 + threadIdx.x;
    int b = blockIdx.y, s = blockIdx.z;
    const float* xr = in + b * K + s * 128;
    const float* wp = w + (size_t)(s * 128) * N + n;
    float acc = 0.f;
    #pragma unroll 8
    for (int k = 0; k < 128; ++k) acc += xr[k] * wp[(size_t)k * N];
    part[(s * 2 + b) * 4096 + n] = acc;
}

__global__ void k_treduce(const float* __restrict__ part,
                          const float* __restrict__ bias,
                          float* __restrict__ out, int N) {
    int n = blockIdx.x * 256 + threadIdx.x;
    int b = blockIdx.y;
    if (n >= N) return;
    float acc = bias[n];
    #pragma unroll
    for (int s = 0; s < 8; ++s) acc += part[(s * 2 + b) * 4096 + n];
    out[b * N + n] = acc;
}

__global__ void k_tswiglu(const float* __restrict__ u, float* __restrict__ s) {
    int i = blockIdx.x * 256 + threadIdx.x;  // 2048 total
    if (i >= 2048) return;
    int b = i >> 10, j = i & 1023;
    float a = u[b * 2048 + j];
    float g = u[b * 2048 + 1024 + j];
    s[b * 1024 + j] = a * (g / (1.f + expf(-g)));
}

// ---------------- rope cos/sin table ---------------------------------------
__global__ void k_ropetab(float2* __restrict__ tab) {
    int idx = blockIdx.x * 256 + threadIdx.x;   // 65536
    int t = idx >> 5, i = idx & 31;
    float inv = powf(10000.f, -(float)i * (1.f / 32.f));
    float sn, cs;
    sincosf((float)t * inv, &sn, &cs);
    tab[idx] = make_float2(cs, sn);
}

// ---------------- fused RMSNorm + adaLN modulation --------------------------
__global__ __launch_bounds__(256) void k_rmsnorm(const float* __restrict__ x,
                                                 const float* __restrict__ g,
                                                 const float* __restrict__ tp,
                                                 int shift_off, int scale_off,
                                                 float* __restrict__ out) {
    int row = blockIdx.x;          // 0..4095
    int b   = row >> 11;
    const float4* xr = (const float4*)(x + row * 1024);
    float4 v = xr[threadIdx.x];
    float ss = v.x * v.x + v.y * v.y + v.z * v.z + v.w * v.w;
    #pragma unroll
    for (int off = 16; off; off >>= 1) ss += __shfl_xor_sync(0xFFFFFFFFu, ss, off);
    __shared__ float wsum[8];
    __shared__ float stot;
    if ((threadIdx.x & 31) == 0) wsum[threadIdx.x >> 5] = ss;
    __syncthreads();
    if (threadIdx.x == 0) {
        float t = 0.f;
        #pragma unroll
        for (int i = 0; i < 8; ++i) t += wsum[i];
        stot = rsqrtf(t * (1.f / 1024.f) + 1.1920928955078125e-7f);
    }
    __syncthreads();
    float r = stot;
    int j = threadIdx.x * 4;
    const float* gg = g + j;
    const float* sc = tp + b * 4096 + scale_off + j;
    const float* sh = tp + b * 4096 + shift_off + j;
    float4 o;
    o.x = v.x * r * gg[0] * (1.f + sc[0]) + sh[0];
    o.y = v.y * r * gg[1] * (1.f + sc[1]) + sh[1];
    o.z = v.z * r * gg[2] * (1.f + sc[2]) + sh[2];
    o.w = v.w * r * gg[3] * (1.f + sc[3]) + sh[3];
    ((float4*)(out + row * 1024))[threadIdx.x] = o;
}

// ---------------- fp16 tensor-core GEMM: cp.async fp32 -> f16 smem ----------
// C[M,N] = A[M,K] @ B[K,N] + bias (+residual) (+rope on cols<2048).
// Block 128x128, BK=16, 8 warps 2x4, warp tile 64x32, m16n8k16 f16, fp32 acc.
// fp32 staged via 3-stage cp.async; per-tile convert pass writes native-f16
// tiles (A [m][24] f16, B [k][136] f16); fragments via ldmatrix(.trans).b16.
#define AS(s, m, k) Asm[((s) * 128 + (m)) * 20 + (k)]
#define BS(s, r, n) Bsm[((s) * 16 + (r)) * 132 + (n)]
#define F32_BYTES ((3 * 128 * 20 + 3 * 16 * 132) * 4)   // 56064
#define A16_OFF   F32_BYTES                              // 128*24*2 = 6144
#define B16_OFF   (A16_OFF + 128 * 24 * 2)               // 16*136*2 = 4352
#define GEMM_SMEM (B16_OFF + 16 * 136 * 2)               // 66560

template <bool RES, bool ROPE>
__global__ __launch_bounds__(256) void k_tgemm(const float* __restrict__ A,
                                               const float* __restrict__ B,
                                               const float* __restrict__ bias,
                                               const float* __restrict__ res,
                                               const float2* __restrict__ rtab,
                                               float* __restrict__ C,
                                               int Nn, int Kn) {
    extern __shared__ __align__(16) float smemraw[];
    float* Asm = smemraw;                    // fp32 [3][128][20]
    float* Bsm = smemraw + 3 * 128 * 20;     // fp32 [3][16][132]
    char*  A16 = (char*)smemraw + A16_OFF;   // f16 [128][24]
    char*  B16 = (char*)smemraw + B16_OFF;   // f16 [16][136]
    const unsigned A16u = (unsigned)__cvta_generic_to_shared(A16);
    const unsigned B16u = (unsigned)__cvta_generic_to_shared(B16);

    const int tid  = threadIdx.x;
    const int lane = tid & 31;
    const int g    = lane >> 2;
    const int t    = lane & 3;
    const int warp = tid >> 5;
    const int wm   = (warp >> 2) * 64;
    const int wn   = (warp & 3) * 32;

    const int row0 = blockIdx.y * 128;
    const int col0 = blockIdx.x * 128;

    // global->fp32-smem load mapping (cp.async)
    const int arow = tid >> 2;         // 0..63 (+64)
    const int ac4  = tid & 3;
    const int brow = tid >> 5;         // 0..7 (+8)
    const int bc4  = tid & 31;

    const float* Ap0 = A + (size_t)(row0 + arow)      * Kn + ac4 * 4;
    const float* Ap1 = A + (size_t)(row0 + arow + 64) * Kn + ac4 * 4;
    const float* Bp0 = B + (size_t)brow       * Nn + col0 + bc4 * 4;
    const float* Bp1 = B + (size_t)(brow + 8) * Nn + col0 + bc4 * 4;

    // convert pass mapping
    const int am = tid & 127;          // A: m row
    const int ah = tid >> 7;           // A: k half (0/1)
    const int bk = tid >> 4;           // B: k row 0..15
    const int bg = tid & 15;           // B: n group of 8

    // ldmatrix lane addressing
    const int a_lm = (lane & 7) + 8 * ((lane >> 3) & 1);   // m within 16
    const int a_lk = ((lane >> 4) & 1) * 16;               // k byte offset
    const int b_lk = ((lane >> 3) & 1) * 8 + (lane & 7);   // k row
    const int b_ln = ((lane >> 4) & 1) * 8;                // n within 16

    float acc[4][4][4];
    #pragma unroll
    for (int mi = 0; mi < 4; ++mi)
        #pragma unroll
        for (int ni = 0; ni < 4; ++ni)
            #pragma unroll
            for (int r = 0; r < 4; ++r) acc[mi][ni][r] = 0.f;

    const int tiles = Kn >> 4;

    #pragma unroll
    for (int s = 0; s < 2; ++s) {
        cp16(&AS(s, arow, ac4 * 4),      Ap0);
        cp16(&AS(s, arow + 64, ac4 * 4), Ap1);
        cp16(&BS(s, brow, bc4 * 4),      Bp0);
        cp16(&BS(s, brow + 8, bc4 * 4),  Bp1);
        cp_commit();
        Ap0 += 16; Ap1 += 16;
        Bp0 += (size_t)16 * Nn; Bp1 += (size_t)16 * Nn;
    }

    for (int i = 0; i < tiles; ++i) {
        const int buf = i % 3;
        cp_wait<1>();
        __syncthreads();                 // fp32 tile i ready; prior compute done
        if (i + 2 < tiles) {
            const int nb = (i + 2) % 3;
            cp16(&AS(nb, arow, ac4 * 4),      Ap0);
            cp16(&AS(nb, arow + 64, ac4 * 4), Ap1);
            cp16(&BS(nb, brow, bc4 * 4),      Bp0);
            cp16(&BS(nb, brow + 8, bc4 * 4),  Bp1);
            Ap0 += 16; Ap1 += 16;
            Bp0 += (size_t)16 * Nn; Bp1 += (size_t)16 * Nn;
        }
        cp_commit();   // always commit (keeps wait<1> semantics on the tail)

        // ---- convert pass: fp32 smem -> f16 smem (once per element) --------
        {
            const float* ar = &AS(buf, am, ah * 8);
            float2 p0 = *(const float2*)(ar + 0);
            float2 p1 = *(const float2*)(ar + 2);
            float2 p2 = *(const float2*)(ar + 4);
            float2 p3 = *(const float2*)(ar + 6);
            uint4 q;
            q.x = pack_f16(p0.x, p0.y);
            q.y = pack_f16(p1.x, p1.y);
            q.z = pack_f16(p2.x, p2.y);
            q.w = pack_f16(p3.x, p3.y);
            *(uint4*)(A16 + am * 48 + ah * 16) = q;

            const float* br = &BS(buf, bk, bg * 8);
            p0 = *(const float2*)(br + 0);
            p1 = *(const float2*)(br + 2);
            p2 = *(const float2*)(br + 4);
            p3 = *(const float2*)(br + 6);
            q.x = pack_f16(p0.x, p0.y);
            q.y = pack_f16(p1.x, p1.y);
            q.z = pack_f16(p2.x, p2.y);
            q.w = pack_f16(p3.x, p3.y);
            *(uint4*)(B16 + bk * 272 + bg * 16) = q;
        }
        __syncthreads();                 // f16 tiles ready

        // ---- fragments via ldmatrix, 16 f16 mmas ---------------------------
        unsigned af[4][4], bf[4][2];
        #pragma unroll
        for (int mi = 0; mi < 4; ++mi) {
            unsigned addr = A16u + (unsigned)((wm + mi * 16 + a_lm) * 48 + a_lk);
            ldsm4(af[mi][0], af[mi][1], af[mi][2], af[mi][3], addr);
        }
        #pragma unroll
        for (int bb = 0; bb < 2; ++bb) {
            unsigned addr = B16u + (unsigned)(b_lk * 272 + (wn + bb * 16 + b_ln) * 2);
            unsigned r0, r1, r2, r3;
            ldsm4t(r0, r1, r2, r3, addr);
            bf[bb * 2][0]     = r0;  bf[bb * 2][1]     = r1;
            bf[bb * 2 + 1][0] = r2;  bf[bb * 2 + 1][1] = r3;
        }
        #pragma unroll
        for (int mi = 0; mi < 4; ++mi)
            #pragma unroll
            for (int ni = 0; ni < 4; ++ni)
                mma_f16(acc[mi][ni], af[mi][0], af[mi][1], af[mi][2], af[mi][3],
                        bf[ni][0], bf[ni][1]);
    }

    // epilogue: bias (+residual) (+rope)
    #pragma unroll
    for (int mi = 0; mi < 4; ++mi) {
        int r_top = row0 + wm + mi * 16 + g;
        int r_bot = r_top + 8;
        #pragma unroll
        for (int ni = 0; ni < 4; ++ni) {
            int c = col0 + wn + ni * 8 + 2 * t;   // even column
            float bx = bias[c], by = bias[c + 1];
            float2 w0 = make_float2(acc[mi][ni][0] + bx, acc[mi][ni][1] + by);
            float2 w1 = make_float2(acc[mi][ni][2] + bx, acc[mi][ni][3] + by);
            if (RES) {
                float2 r0 = *(const float2*)(res + (size_t)r_top * Nn + c);
                float2 r1 = *(const float2*)(res + (size_t)r_bot * Nn + c);
                w0.x += r0.x; w0.y += r0.y;
                w1.x += r1.x; w1.y += r1.y;
            }
            if (ROPE && c < 2048) {            // q,k columns get rope
                int i = (c & 63) >> 1;
                float2 cs0 = rtab[(r_top & 2047) * 32 + i];
                float2 cs1 = rtab[(r_bot & 2047) * 32 + i];
                float a0 = w0.x, a1 = w0.y;
                w0.x = a0 * cs0.x - a1 * cs0.y;
                w0.y = a1 * cs0.x + a0 * cs0.y;
                a0 = w1.x; a1 = w1.y;
                w1.x = a0 * cs1.x - a1 * cs1.y;
                w1.y = a1 * cs1.x + a0 * cs1.y;
            }
            *(float2*)(C + (size_t)r_top * Nn + c) = w0;
            *(float2*)(C + (size_t)r_bot * Nn + c) = w1;
        }
    }
}

// ---------------- tensor-core flash attention, cp.async K/V pipeline --------
#define QP_STR 68
#define KS_STR 68
#define VS_STR 72
#define ATTN_SMEM (64 * (QP_STR + 2 * KS_STR + 2 * VS_STR) * 4)

__global__ __launch_bounds__(128) void k_attn(const float* __restrict__ qkv,
                                              float* __restrict__ out) {
    extern __shared__ float sm[];
    float* QP = sm;                                   // 64*68
    float* Ks = sm + 64 * QP_STR;                     // 2 x 64*68
    float* Vs = sm + 64 * (QP_STR + 2 * KS_STR);      // 2 x 64*72

    const int tid  = threadIdx.x;
    const int lane = tid & 31;
    const int g    = lane >> 2;
    const int t    = lane & 3;
    const int warp = tid >> 5;
    const int m0   = warp * 16;

    const int qt = blockIdx.x, bh = blockIdx.y;
    const int b = bh >> 4, h = bh & 15;
    const int base_tok = b * 2048;

    const int ld_row = tid >> 4;
    const int ld_dc  = (tid & 15) << 2;

    #pragma unroll
    for (int rr = 0; rr < 8; ++rr) {
        int row = ld_row + rr * 8;
        int tok = base_tok + row;
        cp16(Ks + row * KS_STR + ld_dc, qkv + (size_t)tok * 3072 + 1024 + h * 64 + ld_dc);
        cp16(Vs + row * VS_STR + ld_dc, qkv + (size_t)tok * 3072 + 2048 + h * 64 + ld_dc);
    }
    cp_commit();

    #pragma unroll
    for (int f = tid; f < 1024; f += 128) {
        int row = f >> 4, dc = (f & 15) << 2;
        int tok = base_tok + qt * 64 + row;
        float4 q4 = *(const float4*)(qkv + (size_t)tok * 3072 + h * 64 + dc);
        uint4 u;
        u.x = cvt_tf32(q4.x * 0.125f); u.y = cvt_tf32(q4.y * 0.125f);
        u.z = cvt_tf32(q4.z * 0.125f); u.w = cvt_tf32(q4.w * 0.125f);
        *(uint4*)(QP + row * QP_STR + dc) = u;
    }
    __syncthreads();

    unsigned qa[8][4];
    #pragma unroll
    for (int ks = 0; ks < 8; ++ks) {
        const unsigned* q0 = (const unsigned*)(QP + (m0 + g) * QP_STR);
        const unsigned* q1 = (const unsigned*)(QP + (m0 + g + 8) * QP_STR);
        qa[ks][0] = q0[ks * 8 + t];
        qa[ks][1] = q1[ks * 8 + t];
        qa[ks][2] = q0[ks * 8 + t + 4];
        qa[ks][3] = q1[ks * 8 + t + 4];
    }

    float o[8][4];
    #pragma unroll
    for (int j = 0; j < 8; ++j)
        #pragma unroll
        for (int r = 0; r < 4; ++r) o[j][r] = 0.f;
    float M1 = -INFINITY, M2 = -INFINITY, L1 = 0.f, L2 = 0.f;

    for (int kt = 0; kt < 32; ++kt) {
        const int buf = kt & 1;
        float* Kb = Ks + buf * 64 * KS_STR;
        float* Vb = Vs + buf * 64 * VS_STR;

        __syncthreads();
        if (kt + 1 < 32) {
            float* Kn = Ks + (buf ^ 1) * 64 * KS_STR;
            float* Vn = Vs + (buf ^ 1) * 64 * VS_STR;
            #pragma unroll
            for (int rr = 0; rr < 8; ++rr) {
                int row = ld_row + rr * 8;
                int tok = base_tok + (kt + 1) * 64 + row;
                cp16(Kn + row * KS_STR + ld_dc, qkv + (size_t)tok * 3072 + 1024 + h * 64 + ld_dc);
                cp16(Vn + row * VS_STR + ld_dc, qkv + (size_t)tok * 3072 + 2048 + h * 64 + ld_dc);
            }
        }
        cp_commit();
        cp_wait<1>();
        __syncthreads();

        float s[8][4];
        #pragma unroll
        for (int j = 0; j < 8; ++j)
            #pragma unroll
            for (int r = 0; r < 4; ++r) s[j][r] = 0.f;

        #pragma unroll
        for (int ks = 0; ks < 8; ++ks) {
            unsigned kb[8][2];
            #pragma unroll
            for (int j = 0; j < 8; ++j) {
                const unsigned* kr = (const unsigned*)(Kb + (j * 8 + g) * KS_STR);
                kb[j][0] = kr[ks * 8 + t]     + 0x1000u;
                kb[j][1] = kr[ks * 8 + t + 4] + 0x1000u;
            }
            #pragma unroll
            for (int j = 0; j < 8; ++j)
                mma_tf32(s[j], qa[ks][0], qa[ks][1], qa[ks][2], qa[ks][3],
                         kb[j][0], kb[j][1]);
        }

        float mx1 = -INFINITY, mx2 = -INFINITY;
        #pragma unroll
        for (int j = 0; j < 8; ++j) {
            mx1 = fmaxf(mx1, fmaxf(s[j][0], s[j][1]));
            mx2 = fmaxf(mx2, fmaxf(s[j][2], s[j][3]));
        }
        mx1 = fmaxf(mx1, __shfl_xor_sync(0xFFFFFFFFu, mx1, 1));
        mx1 = fmaxf(mx1, __shfl_xor_sync(0xFFFFFFFFu, mx1, 2));
        mx2 = fmaxf(mx2, __shfl_xor_sync(0xFFFFFFFFu, mx2, 1));
        mx2 = fmaxf(mx2, __shfl_xor_sync(0xFFFFFFFFu, mx2, 2));
        float mn1 = fmaxf(M1, mx1), mn2 = fmaxf(M2, mx2);
        float cr1 = __expf(M1 - mn1), cr2 = __expf(M2 - mn2);
        float l1 = 0.f, l2 = 0.f;
        #pragma unroll
        for (int j = 0; j < 8; ++j) {
            s[j][0] = __expf(s[j][0] - mn1);
            s[j][1] = __expf(s[j][1] - mn1);
            s[j][2] = __expf(s[j][2] - mn2);
            s[j][3] = __expf(s[j][3] - mn2);
            l1 += s[j][0] + s[j][1];
            l2 += s[j][2] + s[j][3];
        }
        l1 += __shfl_xor_sync(0xFFFFFFFFu, l1, 1);
        l1 += __shfl_xor_sync(0xFFFFFFFFu, l1, 2);
        l2 += __shfl_xor_sync(0xFFFFFFFFu, l2, 1);
        l2 += __shfl_xor_sync(0xFFFFFFFFu, l2, 2);
        L1 = L1 * cr1 + l1;  M1 = mn1;
        L2 = L2 * cr2 + l2;  M2 = mn2;
        #pragma unroll
        for (int j = 0; j < 8; ++j) {
            o[j][0] *= cr1; o[j][1] *= cr1;
            o[j][2] *= cr2; o[j][3] *= cr2;
        }

        #pragma unroll
        for (int j = 0; j < 8; ++j) {
            unsigned* p0 = (unsigned*)(QP + (m0 + g) * QP_STR);
            unsigned* p1 = (unsigned*)(QP + (m0 + g + 8) * QP_STR);
            p0[j * 8 + 2 * t]     = cvt_tf32(s[j][0]);
            p0[j * 8 + 2 * t + 1] = cvt_tf32(s[j][1]);
            p1[j * 8 + 2 * t]     = cvt_tf32(s[j][2]);
            p1[j * 8 + 2 * t + 1] = cvt_tf32(s[j][3]);
        }
        __syncwarp();

        #pragma unroll
        for (int ks = 0; ks < 8; ++ks) {
            const unsigned* p0 = (const unsigned*)(QP + (m0 + g) * QP_STR);
            const unsigned* p1 = (const unsigned*)(QP + (m0 + g + 8) * QP_STR);
            unsigned pa0 = p0[ks * 8 + t];
            unsigned pa1 = p1[ks * 8 + t];
            unsigned pa2 = p0[ks * 8 + t + 4];
            unsigned pa3 = p1[ks * 8 + t + 4];
            #pragma unroll
            for (int j = 0; j < 8; ++j) {
                const unsigned* vr  = (const unsigned*)(Vb + (ks * 8 + t) * VS_STR);
                const unsigned* vr4 = (const unsigned*)(Vb + (ks * 8 + t + 4) * VS_STR);
                unsigned vb0 = vr[j * 8 + g]  + 0x1000u;
                unsigned vb1 = vr4[j * 8 + g] + 0x1000u;
                mma_tf32(o[j], pa0, pa1, pa2, pa3, vb0, vb1);
            }
        }
    }

    float r1 = 1.f / L1, r2 = 1.f / L2;
    int row1 = base_tok + qt * 64 + m0 + g;
    int row2 = row1 + 8;
    #pragma unroll
    for (int j = 0; j < 8; ++j) {
        int c = h * 64 + j * 8 + 2 * t;
        *(float2*)(out + (size_t)row1 * 1024 + c) = make_float2(o[j][0] * r1, o[j][1] * r1);
        *(float2*)(out + (size_t)row2 * 1024 + c) = make_float2(o[j][2] * r2, o[j][3] * r2);
    }
}

// ---------------- SwiGLU for FFN -------------------------------------------
__global__ void k_swiglu(const float* __restrict__ u, float* __restrict__ s) {
    int idx = blockIdx.x * 256 + threadIdx.x;
    int m = idx >> 10, c4 = (idx & 1023) << 2;
    float4 a = *(const float4*)(u + (size_t)m * 8192 + c4);
    float4 g = *(const float4*)(u + (size_t)m * 8192 + 4096 + c4);
    float4 o;
    o.x = a.x * (g.x / (1.f + __expf(-g.x)));
    o.y = a.y * (g.y / (1.f + __expf(-g.y)));
    o.z = a.z * (g.z / (1.f + __expf(-g.z)));
    o.w = a.w * (g.w / (1.f + __expf(-g.w)));
    *(float4*)(s + (size_t)m * 4096 + c4) = o;
}

// ---------------- launcher --------------------------------------------------
extern "C" void kernel_launch(void* const* d_in, const int* in_sizes, int n_in,
                              void* d_out, int out_size) {
    const float* x     = (const float*)d_in[0];
    const float* temb  = (const float*)d_in[1];
    const float* g1    = (const float*)d_in[2];
    const float* g2    = (const float*)d_in[3];
    const float* w_qkv = (const float*)d_in[4];
    const float* b_qkv = (const float*)d_in[5];
    const float* w_ao  = (const float*)d_in[6];
    const float* b_ao  = (const float*)d_in[7];
    const float* w_fc  = (const float*)d_in[8];
    const float* b_fc  = (const float*)d_in[9];
    const float* w_fo  = (const float*)d_in[10];
    const float* b_fo  = (const float*)d_in[11];
    const float* w_t1  = (const float*)d_in[12];
    const float* b_t1  = (const float*)d_in[13];
    const float* w_t2  = (const float*)d_in[14];
    const float* b_t2  = (const float*)d_in[15];
    float* out = (float*)d_out;

    float *tpu, *tps, *tp, *part, *h, *qkv, *att, *x1, *u, *sw;
    float2* rtab;
    cudaGetSymbolAddress((void**)&tpu,  g_tpu);
    cudaGetSymbolAddress((void**)&tps,  g_tps);
    cudaGetSymbolAddress((void**)&tp,   g_tp);
    cudaGetSymbolAddress((void**)&part, g_part);
    cudaGetSymbolAddress((void**)&h,    g_h);
    cudaGetSymbolAddress((void**)&qkv,  g_qkv);
    cudaGetSymbolAddress((void**)&att,  g_att);
    cudaGetSymbolAddress((void**)&x1,   g_x1);
    cudaGetSymbolAddress((void**)&u,    g_u);
    cudaGetSymbolAddress((void**)&sw,   g_sw);
    cudaGetSymbolAddress((void**)&rtab, g_ropetab);

    cudaFuncSetAttribute(k_attn, cudaFuncAttributeMaxDynamicSharedMemorySize, ATTN_SMEM);
    cudaFuncSetAttribute(k_tgemm<false, true>,  cudaFuncAttributeMaxDynamicSharedMemorySize, GEMM_SMEM);
    cudaFuncSetAttribute(k_tgemm<true, false>,  cudaFuncAttributeMaxDynamicSharedMemorySize, GEMM_SMEM);
    cudaFuncSetAttribute(k_tgemm<false, false>, cudaFuncAttributeMaxDynamicSharedMemorySize, GEMM_SMEM);

    // rope table + time-conditioning MLP (split-K, deterministic)
    k_ropetab<<<256, 256>>>(rtab);
    k_tpart<<<dim3(16, 2, 8), 128>>>(temb, w_t1, part, 1024, 2048);
    k_treduce<<<dim3(8, 2), 256>>>(part, b_t1, tpu, 2048);
    k_tswiglu<<<8, 256>>>(tpu, tps);
    k_tpart<<<dim3(32, 2, 8), 128>>>(tps, w_t2, part, 1024, 4096);
    k_treduce<<<dim3(16, 2), 256>>>(part, b_t2, tp, 4096);

    // attention branch
    k_rmsnorm<<<4096, 256>>>(x, g1, tp, 0, 1024, h);
    k_tgemm<false, true><<<dim3(24, 32), 256, GEMM_SMEM>>>(h, w_qkv, b_qkv, nullptr, rtab, qkv, 3072, 1024);
    k_attn<<<dim3(32, 32), 128, ATTN_SMEM>>>(qkv, att);
    k_tgemm<true, false><<<dim3(8, 32), 256, GEMM_SMEM>>>(att, w_ao, b_ao, x, rtab, x1, 1024, 1024);

    // FFN branch
    k_rmsnorm<<<4096, 256>>>(x1, g2, tp, 2048, 3072, h);
    k_tgemm<false, false><<<dim3(64, 32), 256, GEMM_SMEM>>>(h, w_fc, b_fc, nullptr, rtab, u, 8192, 1024);
    k_swiglu<<<16384, 256>>>(u, sw);
    k_tgemm<true, false><<<dim3(8, 32), 256, GEMM_SMEM>>>(sw, w_fo, b_fo, x1, rtab, out, 1024, 4096);
}

// round 16
// speedup vs baseline: 1.1957x; 1.0031x over previous
#include <cuda_runtime.h>
#include <math.h>

// Problem constants: B=2, T=2048, D=1024, H=16, hd=64, M = B*T = 4096
#define MROWS 4096

// ---------------- scratch (device globals; no allocation allowed) ----------
__device__ float g_tpu [2 * 2048];       // time MLP hidden
__device__ float g_tps [2 * 1024];       // time MLP after swiglu
__device__ float g_tp  [2 * 4096];       // shift1|scale1|shift2|scale2
__device__ float g_part[8 * 2 * 4096];   // split-K partials for time MLP
__device__ float g_h   [MROWS * 1024];   // normed/modulated activations
__device__ float g_qkv [MROWS * 3072];   // qkv projections (rope fused)
__device__ float g_att [MROWS * 1024];   // attention output (b,t,h,d)
__device__ float g_x1  [MROWS * 1024];   // x after attention residual
__device__ float g_u   [MROWS * 8192];   // ffn pre-activation
__device__ float g_sw  [MROWS * 4096];   // ffn post-swiglu
__device__ float2 g_ropetab[2048 * 32];  // (cos, sin) per (pos, pair)

// ---------------- PTX helpers ----------------------------------------------
__device__ __forceinline__ unsigned cvt_tf32(float f) {
    unsigned u;
    asm("cvt.rna.tf32.f32 %0, %1;" : "=r"(u) : "f"(f));
    return u;
}

// pack two fp32 into f16x2 (lo -> low half, hi -> high half), RN
__device__ __forceinline__ unsigned pack_f16(float lo, float hi) {
    unsigned d;
    asm("cvt.rn.f16x2.f32 %0, %1, %2;" : "=r"(d) : "f"(hi), "f"(lo));
    return d;
}

__device__ __forceinline__ void mma_tf32(float* c, unsigned a0, unsigned a1,
                                         unsigned a2, unsigned a3,
                                         unsigned b0, unsigned b1) {
    asm volatile(
        "mma.sync.aligned.m16n8k8.row.col.f32.tf32.tf32.f32 "
        "{%0,%1,%2,%3}, {%4,%5,%6,%7}, {%8,%9}, {%0,%1,%2,%3};\n"
        : "+f"(c[0]), "+f"(c[1]), "+f"(c[2]), "+f"(c[3])
        : "r"(a0), "r"(a1), "r"(a2), "r"(a3), "r"(b0), "r"(b1));
}

__device__ __forceinline__ void mma_f16(float* c, unsigned a0, unsigned a1,
                                        unsigned a2, unsigned a3,
                                        unsigned b0, unsigned b1) {
    asm volatile(
        "mma.sync.aligned.m16n8k16.row.col.f32.f16.f16.f32 "
        "{%0,%1,%2,%3}, {%4,%5,%6,%7}, {%8,%9}, {%0,%1,%2,%3};\n"
        : "+f"(c[0]), "+f"(c[1]), "+f"(c[2]), "+f"(c[3])
        : "r"(a0), "r"(a1), "r"(a2), "r"(a3), "r"(b0), "r"(b1));
}

__device__ __forceinline__ void ldsm4(unsigned& r0, unsigned& r1,
                                      unsigned& r2, unsigned& r3, unsigned addr) {
    asm volatile("ldmatrix.sync.aligned.m8n8.x4.shared.b16 {%0,%1,%2,%3}, [%4];"
                 : "=r"(r0), "=r"(r1), "=r"(r2), "=r"(r3) : "r"(addr));
}

__device__ __forceinline__ void ldsm4t(unsigned& r0, unsigned& r1,
                                       unsigned& r2, unsigned& r3, unsigned addr) {
    asm volatile("ldmatrix.sync.aligned.m8n8.x4.trans.shared.b16 {%0,%1,%2,%3}, [%4];"
                 : "=r"(r0), "=r"(r1), "=r"(r2), "=r"(r3) : "r"(addr));
}

__device__ __forceinline__ void cp16(void* dst, const void* src) {
    unsigned ds = (unsigned)__cvta_generic_to_shared(dst);
    asm volatile("cp.async.cg.shared.global [%0], [%1], 16;\n" :: "r"(ds), "l"(src));
}
__device__ __forceinline__ void cp_commit() {
    asm volatile("cp.async.commit_group;\n");
}
template <int N>
__device__ __forceinline__ void cp_wait() {
    asm volatile("cp.async.wait_group %0;\n" :: "n"(N));
}

// ---------------- time-MLP: split-K partial GEMM + reduce -------------------
__global__ __launch_bounds__(128) void k_tpart(const float* __restrict__ in,
                                               const float* __restrict__ w,
                                               float* __restrict__ part,
                                               int K, int N) {
    int n = blockIdx.x * 128 + threadIdx.x;
    int b = blockIdx.y, s = blockIdx.z;
    const float* xr = in + b * K + s * 128;
    const float* wp = w + (size_t)(s * 128) * N + n;
    float acc = 0.f;
    #pragma unroll 8
    for (int k = 0; k < 128; ++k) acc += xr[k] * wp[(size_t)k * N];
    part[(s * 2 + b) * 4096 + n] = acc;
}

__global__ void k_treduce(const float* __restrict__ part,
                          const float* __restrict__ bias,
                          float* __restrict__ out, int N) {
    int n = blockIdx.x * 256 + threadIdx.x;
    int b = blockIdx.y;
    if (n >= N) return;
    float acc = bias[n];
    #pragma unroll
    for (int s = 0; s < 8; ++s) acc += part[(s * 2 + b) * 4096 + n];
    out[b * N + n] = acc;
}

__global__ void k_tswiglu(const float* __restrict__ u, float* __restrict__ s) {
    int i = blockIdx.x * 256 + threadIdx.x;  // 2048 total
    if (i >= 2048) return;
    int b = i >> 10, j = i & 1023;
    float a = u[b * 2048 + j];
    float g = u[b * 2048 + 1024 + j];
    s[b * 1024 + j] = a * (g / (1.f + expf(-g)));
}

// ---------------- rope cos/sin table ---------------------------------------
__global__ void k_ropetab(float2* __restrict__ tab) {
    int idx = blockIdx.x * 256 + threadIdx.x;   // 65536
    int t = idx >> 5, i = idx & 31;
    float inv = powf(10000.f, -(float)i * (1.f / 32.f));
    float sn, cs;
    sincosf((float)t * inv, &sn, &cs);
    tab[idx] = make_float2(cs, sn);
}

// ---------------- fused RMSNorm + adaLN modulation --------------------------
__global__ __launch_bounds__(256) void k_rmsnorm(const float* __restrict__ x,
                                                 const float* __restrict__ g,
                                                 const float* __restrict__ tp,
                                                 int shift_off, int scale_off,
                                                 float* __restrict__ out) {
    int row = blockIdx.x;          // 0..4095
    int b   = row >> 11;
    const float4* xr = (const float4*)(x + row * 1024);
    float4 v = xr[threadIdx.x];
    float ss = v.x * v.x + v.y * v.y + v.z * v.z + v.w * v.w;
    #pragma unroll
    for (int off = 16; off; off >>= 1) ss += __shfl_xor_sync(0xFFFFFFFFu, ss, off);
    __shared__ float wsum[8];
    __shared__ float stot;
    if ((threadIdx.x & 31) == 0) wsum[threadIdx.x >> 5] = ss;
    __syncthreads();
    if (threadIdx.x == 0) {
        float t = 0.f;
        #pragma unroll
        for (int i = 0; i < 8; ++i) t += wsum[i];
        stot = rsqrtf(t * (1.f / 1024.f) + 1.1920928955078125e-7f);
    }
    __syncthreads();
    float r = stot;
    int j = threadIdx.x * 4;
    const float* gg = g + j;
    const float* sc = tp + b * 4096 + scale_off + j;
    const float* sh = tp + b * 4096 + shift_off + j;
    float4 o;
    o.x = v.x * r * gg[0] * (1.f + sc[0]) + sh[0];
    o.y = v.y * r * gg[1] * (1.f + sc[1]) + sh[1];
    o.z = v.z * r * gg[2] * (1.f + sc[2]) + sh[2];
    o.w = v.w * r * gg[3] * (1.f + sc[3]) + sh[3];
    ((float4*)(out + row * 1024))[threadIdx.x] = o;
}

// ---------------- fp16 tensor-core GEMM: cp.async fp32 -> f16 smem ----------
// C[M,N] = A[M,K] @ B[K,N] + bias (+residual) (+rope on cols<2048).
// Block 128x128, BK=16, 8 warps 2x4, warp tile 64x32, m16n8k16 f16, fp32 acc.
// fp32 staged via 3-stage cp.async; per-tile convert pass writes native-f16
// tiles (A [m][24] f16, B [k][136] f16); fragments via ldmatrix(.trans).b16.
#define AS(s, m, k) Asm[((s) * 128 + (m)) * 20 + (k)]
#define BS(s, r, n) Bsm[((s) * 16 + (r)) * 132 + (n)]
#define F32_BYTES ((3 * 128 * 20 + 3 * 16 * 132) * 4)   // 56064
#define A16_OFF   F32_BYTES                              // 128*24*2 = 6144
#define B16_OFF   (A16_OFF + 128 * 24 * 2)               // 16*136*2 = 4352
#define GEMM_SMEM (B16_OFF + 16 * 136 * 2)               // 66560

template <bool RES, bool ROPE>
__global__ __launch_bounds__(256) void k_tgemm(const float* __restrict__ A,
                                               const float* __restrict__ B,
                                               const float* __restrict__ bias,
                                               const float* __restrict__ res,
                                               const float2* __restrict__ rtab,
                                               float* __restrict__ C,
                                               int Nn, int Kn) {
    extern __shared__ __align__(16) float smemraw[];
    float* Asm = smemraw;                    // fp32 [3][128][20]
    float* Bsm = smemraw + 3 * 128 * 20;     // fp32 [3][16][132]
    char*  A16 = (char*)smemraw + A16_OFF;   // f16 [128][24]
    char*  B16 = (char*)smemraw + B16_OFF;   // f16 [16][136]
    const unsigned A16u = (unsigned)__cvta_generic_to_shared(A16);
    const unsigned B16u = (unsigned)__cvta_generic_to_shared(B16);

    const int tid  = threadIdx.x;
    const int lane = tid & 31;
    const int g    = lane >> 2;
    const int t    = lane & 3;
    const int warp = tid >> 5;
    const int wm   = (warp >> 2) * 64;
    const int wn   = (warp & 3) * 32;

    const int row0 = blockIdx.y * 128;
    const int col0 = blockIdx.x * 128;

    // global->fp32-smem load mapping (cp.async)
    const int arow = tid >> 2;         // 0..63 (+64)
    const int ac4  = tid & 3;
    const int brow = tid >> 5;         // 0..7 (+8)
    const int bc4  = tid & 31;

    const float* Ap0 = A + (size_t)(row0 + arow)      * Kn + ac4 * 4;
    const float* Ap1 = A + (size_t)(row0 + arow + 64) * Kn + ac4 * 4;
    const float* Bp0 = B + (size_t)brow       * Nn + col0 + bc4 * 4;
    const float* Bp1 = B + (size_t)(brow + 8) * Nn + col0 + bc4 * 4;

    // convert pass mapping
    const int am = tid & 127;          // A: m row
    const int ah = tid >> 7;           // A: k half (0/1)
    const int bk = tid >> 4;           // B: k row 0..15
    const int bg = tid & 15;           // B: n group of 8

    // ldmatrix lane addressing
    const int a_lm = (lane & 7) + 8 * ((lane >> 3) & 1);   // m within 16
    const int a_lk = ((lane >> 4) & 1) * 16;               // k byte offset
    const int b_lk = ((lane >> 3) & 1) * 8 + (lane & 7);   // k row
    const int b_ln = ((lane >> 4) & 1) * 8;                // n within 16

    float acc[4][4][4];
    #pragma unroll
    for (int mi = 0; mi < 4; ++mi)
        #pragma unroll
        for (int ni = 0; ni < 4; ++ni)
            #pragma unroll
            for (int r = 0; r < 4; ++r) acc[mi][ni][r] = 0.f;

    const int tiles = Kn >> 4;

    #pragma unroll
    for (int s = 0; s < 2; ++s) {
        cp16(&AS(s, arow, ac4 * 4),      Ap0);
        cp16(&AS(s, arow + 64, ac4 * 4), Ap1);
        cp16(&BS(s, brow, bc4 * 4),      Bp0);
        cp16(&BS(s, brow + 8, bc4 * 4),  Bp1);
        cp_commit();
        Ap0 += 16; Ap1 += 16;
        Bp0 += (size_t)16 * Nn; Bp1 += (size_t)16 * Nn;
    }

    for (int i = 0; i < tiles; ++i) {
        const int buf = i % 3;
        cp_wait<1>();
        __syncthreads();                 // fp32 tile i ready; prior compute done
        if (i + 2 < tiles) {
            const int nb = (i + 2) % 3;
            cp16(&AS(nb, arow, ac4 * 4),      Ap0);
            cp16(&AS(nb, arow + 64, ac4 * 4), Ap1);
            cp16(&BS(nb, brow, bc4 * 4),      Bp0);
            cp16(&BS(nb, brow + 8, bc4 * 4),  Bp1);
            Ap0 += 16; Ap1 += 16;
            Bp0 += (size_t)16 * Nn; Bp1 += (size_t)16 * Nn;
        }
        cp_commit();   // always commit (keeps wait<1> semantics on the tail)

        // ---- convert pass: fp32 smem -> f16 smem (once per element) --------
        {
            const float* ar = &AS(buf, am, ah * 8);
            float2 p0 = *(const float2*)(ar + 0);
            float2 p1 = *(const float2*)(ar + 2);
            float2 p2 = *(const float2*)(ar + 4);
            float2 p3 = *(const float2*)(ar + 6);
            uint4 q;
            q.x = pack_f16(p0.x, p0.y);
            q.y = pack_f16(p1.x, p1.y);
            q.z = pack_f16(p2.x, p2.y);
            q.w = pack_f16(p3.x, p3.y);
            *(uint4*)(A16 + am * 48 + ah * 16) = q;

            const float* br = &BS(buf, bk, bg * 8);
            p0 = *(const float2*)(br + 0);
            p1 = *(const float2*)(br + 2);
            p2 = *(const float2*)(br + 4);
            p3 = *(const float2*)(br + 6);
            q.x = pack_f16(p0.x, p0.y);
            q.y = pack_f16(p1.x, p1.y);
            q.z = pack_f16(p2.x, p2.y);
            q.w = pack_f16(p3.x, p3.y);
            *(uint4*)(B16 + bk * 272 + bg * 16) = q;
        }
        __syncthreads();                 // f16 tiles ready

        // ---- fragments via ldmatrix, 16 f16 mmas ---------------------------
        unsigned af[4][4], bf[4][2];
        #pragma unroll
        for (int mi = 0; mi < 4; ++mi) {
            unsigned addr = A16u + (unsigned)((wm + mi * 16 + a_lm) * 48 + a_lk);
            ldsm4(af[mi][0], af[mi][1], af[mi][2], af[mi][3], addr);
        }
        #pragma unroll
        for (int bb = 0; bb < 2; ++bb) {
            unsigned addr = B16u + (unsigned)(b_lk * 272 + (wn + bb * 16 + b_ln) * 2);
            unsigned r0, r1, r2, r3;
            ldsm4t(r0, r1, r2, r3, addr);
            bf[bb * 2][0]     = r0;  bf[bb * 2][1]     = r1;
            bf[bb * 2 + 1][0] = r2;  bf[bb * 2 + 1][1] = r3;
        }
        #pragma unroll
        for (int mi = 0; mi < 4; ++mi)
            #pragma unroll
            for (int ni = 0; ni < 4; ++ni)
                mma_f16(acc[mi][ni], af[mi][0], af[mi][1], af[mi][2], af[mi][3],
                        bf[ni][0], bf[ni][1]);
    }

    // epilogue: bias (+residual) (+rope)
    #pragma unroll
    for (int mi = 0; mi < 4; ++mi) {
        int r_top = row0 + wm + mi * 16 + g;
        int r_bot = r_top + 8;
        #pragma unroll
        for (int ni = 0; ni < 4; ++ni) {
            int c = col0 + wn + ni * 8 + 2 * t;   // even column
            float bx = bias[c], by = bias[c + 1];
            float2 w0 = make_float2(acc[mi][ni][0] + bx, acc[mi][ni][1] + by);
            float2 w1 = make_float2(acc[mi][ni][2] + bx, acc[mi][ni][3] + by);
            if (RES) {
                float2 r0 = *(const float2*)(res + (size_t)r_top * Nn + c);
                float2 r1 = *(const float2*)(res + (size_t)r_bot * Nn + c);
                w0.x += r0.x; w0.y += r0.y;
                w1.x += r1.x; w1.y += r1.y;
            }
            if (ROPE && c < 2048) {            // q,k columns get rope
                int i = (c & 63) >> 1;
                float2 cs0 = rtab[(r_top & 2047) * 32 + i];
                float2 cs1 = rtab[(r_bot & 2047) * 32 + i];
                float a0 = w0.x, a1 = w0.y;
                w0.x = a0 * cs0.x - a1 * cs0.y;
                w0.y = a1 * cs0.x + a0 * cs0.y;
                a0 = w1.x; a1 = w1.y;
                w1.x = a0 * cs1.x - a1 * cs1.y;
                w1.y = a1 * cs1.x + a0 * cs1.y;
            }
            *(float2*)(C + (size_t)r_top * Nn + c) = w0;
            *(float2*)(C + (size_t)r_bot * Nn + c) = w1;
        }
    }
}

// ---------------- tensor-core flash attention, cp.async K/V pipeline --------
#define QP_STR 68
#define KS_STR 68
#define VS_STR 72
#define ATTN_SMEM (64 * (QP_STR + 2 * KS_STR + 2 * VS_STR) * 4)

__global__ __launch_bounds__(128) void k_attn(const float* __restrict__ qkv,
                                              float* __restrict__ out) {
    extern __shared__ float sm[];
    float* QP = sm;                                   // 64*68
    float* Ks = sm + 64 * QP_STR;                     // 2 x 64*68
    float* Vs = sm + 64 * (QP_STR + 2 * KS_STR);      // 2 x 64*72

    const int tid  = threadIdx.x;
    const int lane = tid & 31;
    const int g    = lane >> 2;
    const int t    = lane & 3;
    const int warp = tid >> 5;
    const int m0   = warp * 16;

    const int qt = blockIdx.x, bh = blockIdx.y;
    const int b = bh >> 4, h = bh & 15;
    const int base_tok = b * 2048;

    const int ld_row = tid >> 4;
    const int ld_dc  = (tid & 15) << 2;

    #pragma unroll
    for (int rr = 0; rr < 8; ++rr) {
        int row = ld_row + rr * 8;
        int tok = base_tok + row;
        cp16(Ks + row * KS_STR + ld_dc, qkv + (size_t)tok * 3072 + 1024 + h * 64 + ld_dc);
        cp16(Vs + row * VS_STR + ld_dc, qkv + (size_t)tok * 3072 + 2048 + h * 64 + ld_dc);
    }
    cp_commit();

    #pragma unroll
    for (int f = tid; f < 1024; f += 128) {
        int row = f >> 4, dc = (f & 15) << 2;
        int tok = base_tok + qt * 64 + row;
        float4 q4 = *(const float4*)(qkv + (size_t)tok * 3072 + h * 64 + dc);
        uint4 u;
        u.x = cvt_tf32(q4.x * 0.125f); u.y = cvt_tf32(q4.y * 0.125f);
        u.z = cvt_tf32(q4.z * 0.125f); u.w = cvt_tf32(q4.w * 0.125f);
        *(uint4*)(QP + row * QP_STR + dc) = u;
    }
    __syncthreads();

    unsigned qa[8][4];
    #pragma unroll
    for (int ks = 0; ks < 8; ++ks) {
        const unsigned* q0 = (const unsigned*)(QP + (m0 + g) * QP_STR);
        const unsigned* q1 = (const unsigned*)(QP + (m0 + g + 8) * QP_STR);
        qa[ks][0] = q0[ks * 8 + t];
        qa[ks][1] = q1[ks * 8 + t];
        qa[ks][2] = q0[ks * 8 + t + 4];
        qa[ks][3] = q1[ks * 8 + t + 4];
    }

    float o[8][4];
    #pragma unroll
    for (int j = 0; j < 8; ++j)
        #pragma unroll
        for (int r = 0; r < 4; ++r) o[j][r] = 0.f;
    float M1 = -INFINITY, M2 = -INFINITY, L1 = 0.f, L2 = 0.f;

    for (int kt = 0; kt < 32; ++kt) {
        const int buf = kt & 1;
        float* Kb = Ks + buf * 64 * KS_STR;
        float* Vb = Vs + buf * 64 * VS_STR;

        __syncthreads();
        if (kt + 1 < 32) {
            float* Kn = Ks + (buf ^ 1) * 64 * KS_STR;
            float* Vn = Vs + (buf ^ 1) * 64 * VS_STR;
            #pragma unroll
            for (int rr = 0; rr < 8; ++rr) {
                int row = ld_row + rr * 8;
                int tok = base_tok + (kt + 1) * 64 + row;
                cp16(Kn + row * KS_STR + ld_dc, qkv + (size_t)tok * 3072 + 1024 + h * 64 + ld_dc);
                cp16(Vn + row * VS_STR + ld_dc, qkv + (size_t)tok * 3072 + 2048 + h * 64 + ld_dc);
            }
        }
        cp_commit();
        cp_wait<1>();
        __syncthreads();

        float s[8][4];
        #pragma unroll
        for (int j = 0; j < 8; ++j)
            #pragma unroll
            for (int r = 0; r < 4; ++r) s[j][r] = 0.f;

        #pragma unroll
        for (int ks = 0; ks < 8; ++ks) {
            unsigned kb[8][2];
            #pragma unroll
            for (int j = 0; j < 8; ++j) {
                const unsigned* kr = (const unsigned*)(Kb + (j * 8 + g) * KS_STR);
                kb[j][0] = kr[ks * 8 + t]     + 0x1000u;
                kb[j][1] = kr[ks * 8 + t + 4] + 0x1000u;
            }
            #pragma unroll
            for (int j = 0; j < 8; ++j)
                mma_tf32(s[j], qa[ks][0], qa[ks][1], qa[ks][2], qa[ks][3],
                         kb[j][0], kb[j][1]);
        }

        float mx1 = -INFINITY, mx2 = -INFINITY;
        #pragma unroll
        for (int j = 0; j < 8; ++j) {
            mx1 = fmaxf(mx1, fmaxf(s[j][0], s[j][1]));
            mx2 = fmaxf(mx2, fmaxf(s[j][2], s[j][3]));
        }
        mx1 = fmaxf(mx1, __shfl_xor_sync(0xFFFFFFFFu, mx1, 1));
        mx1 = fmaxf(mx1, __shfl_xor_sync(0xFFFFFFFFu, mx1, 2));
        mx2 = fmaxf(mx2, __shfl_xor_sync(0xFFFFFFFFu, mx2, 1));
        mx2 = fmaxf(mx2, __shfl_xor_sync(0xFFFFFFFFu, mx2, 2));
        float mn1 = fmaxf(M1, mx1), mn2 = fmaxf(M2, mx2);
        float cr1 = __expf(M1 - mn1), cr2 = __expf(M2 - mn2);
        float l1 = 0.f, l2 = 0.f;
        #pragma unroll
        for (int j = 0; j < 8; ++j) {
            s[j][0] = __expf(s[j][0] - mn1);
            s[j][1] = __expf(s[j][1] - mn1);
            s[j][2] = __expf(s[j][2] - mn2);
            s[j][3] = __expf(s[j][3] - mn2);
            l1 += s[j][0] + s[j][1];
            l2 += s[j][2] + s[j][3];
        }
        l1 += __shfl_xor_sync(0xFFFFFFFFu, l1, 1);
        l1 += __shfl_xor_sync(0xFFFFFFFFu, l1, 2);
        l2 += __shfl_xor_sync(0xFFFFFFFFu, l2, 1);
        l2 += __shfl_xor_sync(0xFFFFFFFFu, l2, 2);
        L1 = L1 * cr1 + l1;  M1 = mn1;
        L2 = L2 * cr2 + l2;  M2 = mn2;
        #pragma unroll
        for (int j = 0; j < 8; ++j) {
            o[j][0] *= cr1; o[j][1] *= cr1;
            o[j][2] *= cr2; o[j][3] *= cr2;
        }

        #pragma unroll
        for (int j = 0; j < 8; ++j) {
            unsigned* p0 = (unsigned*)(QP + (m0 + g) * QP_STR);
            unsigned* p1 = (unsigned*)(QP + (m0 + g + 8) * QP_STR);
            p0[j * 8 + 2 * t]     = cvt_tf32(s[j][0]);
            p0[j * 8 + 2 * t + 1] = cvt_tf32(s[j][1]);
            p1[j * 8 + 2 * t]     = cvt_tf32(s[j][2]);
            p1[j * 8 + 2 * t + 1] = cvt_tf32(s[j][3]);
        }
        __syncwarp();

        #pragma unroll
        for (int ks = 0; ks < 8; ++ks) {
            const unsigned* p0 = (const unsigned*)(QP + (m0 + g) * QP_STR);
            const unsigned* p1 = (const unsigned*)(QP + (m0 + g + 8) * QP_STR);
            unsigned pa0 = p0[ks * 8 + t];
            unsigned pa1 = p1[ks * 8 + t];
            unsigned pa2 = p0[ks * 8 + t + 4];
            unsigned pa3 = p1[ks * 8 + t + 4];
            #pragma unroll
            for (int j = 0; j < 8; ++j) {
                const unsigned* vr  = (const unsigned*)(Vb + (ks * 8 + t) * VS_STR);
                const unsigned* vr4 = (const unsigned*)(Vb + (ks * 8 + t + 4) * VS_STR);
                unsigned vb0 = vr[j * 8 + g]  + 0x1000u;
                unsigned vb1 = vr4[j * 8 + g] + 0x1000u;
                mma_tf32(o[j], pa0, pa1, pa2, pa3, vb0, vb1);
            }
        }
    }

    float r1 = 1.f / L1, r2 = 1.f / L2;
    int row1 = base_tok + qt * 64 + m0 + g;
    int row2 = row1 + 8;
    #pragma unroll
    for (int j = 0; j < 8; ++j) {
        int c = h * 64 + j * 8 + 2 * t;
        *(float2*)(out + (size_t)row1 * 1024 + c) = make_float2(o[j][0] * r1, o[j][1] * r1);
        *(float2*)(out + (size_t)row2 * 1024 + c) = make_float2(o[j][2] * r2, o[j][3] * r2);
    }
}

// ---------------- SwiGLU for FFN -------------------------------------------
__global__ void k_swiglu(const float* __restrict__ u, float* __restrict__ s) {
    int idx = blockIdx.x * 256 + threadIdx.x;
    int m = idx >> 10, c4 = (idx & 1023) << 2;
    float4 a = *(const float4*)(u + (size_t)m * 8192 + c4);
    float4 g = *(const float4*)(u + (size_t)m * 8192 + 4096 + c4);
    float4 o;
    o.x = a.x * (g.x / (1.f + __expf(-g.x)));
    o.y = a.y * (g.y / (1.f + __expf(-g.y)));
    o.z = a.z * (g.z / (1.f + __expf(-g.z)));
    o.w = a.w * (g.w / (1.f + __expf(-g.w)));
    *(float4*)(s + (size_t)m * 4096 + c4) = o;
}

// ---------------- launcher --------------------------------------------------
extern "C" void kernel_launch(void* const* d_in, const int* in_sizes, int n_in,
                              void* d_out, int out_size) {
    const float* x     = (const float*)d_in[0];
    const float* temb  = (const float*)d_in[1];
    const float* g1    = (const float*)d_in[2];
    const float* g2    = (const float*)d_in[3];
    const float* w_qkv = (const float*)d_in[4];
    const float* b_qkv = (const float*)d_in[5];
    const float* w_ao  = (const float*)d_in[6];
    const float* b_ao  = (const float*)d_in[7];
    const float* w_fc  = (const float*)d_in[8];
    const float* b_fc  = (const float*)d_in[9];
    const float* w_fo  = (const float*)d_in[10];
    const float* b_fo  = (const float*)d_in[11];
    const float* w_t1  = (const float*)d_in[12];
    const float* b_t1  = (const float*)d_in[13];
    const float* w_t2  = (const float*)d_in[14];
    const float* b_t2  = (const float*)d_in[15];
    float* out = (float*)d_out;

    float *tpu, *tps, *tp, *part, *h, *qkv, *att, *x1, *u, *sw;
    float2* rtab;
    cudaGetSymbolAddress((void**)&tpu,  g_tpu);
    cudaGetSymbolAddress((void**)&tps,  g_tps);
    cudaGetSymbolAddress((void**)&tp,   g_tp);
    cudaGetSymbolAddress((void**)&part, g_part);
    cudaGetSymbolAddress((void**)&h,    g_h);
    cudaGetSymbolAddress((void**)&qkv,  g_qkv);
    cudaGetSymbolAddress((void**)&att,  g_att);
    cudaGetSymbolAddress((void**)&x1,   g_x1);
    cudaGetSymbolAddress((void**)&u,    g_u);
    cudaGetSymbolAddress((void**)&sw,   g_sw);
    cudaGetSymbolAddress((void**)&rtab, g_ropetab);

    cudaFuncSetAttribute(k_attn, cudaFuncAttributeMaxDynamicSharedMemorySize, ATTN_SMEM);
    cudaFuncSetAttribute(k_tgemm<false, true>,  cudaFuncAttributeMaxDynamicSharedMemorySize, GEMM_SMEM);
    cudaFuncSetAttribute(k_tgemm<true, false>,  cudaFuncAttributeMaxDynamicSharedMemorySize, GEMM_SMEM);
    cudaFuncSetAttribute(k_tgemm<false, false>, cudaFuncAttributeMaxDynamicSharedMemorySize, GEMM_SMEM);

    // rope table + time-conditioning MLP (split-K, deterministic)
    k_ropetab<<<256, 256>>>(rtab);
    k_tpart<<<dim3(16, 2, 8), 128>>>(temb, w_t1, part, 1024, 2048);
    k_treduce<<<dim3(8, 2), 256>>>(part, b_t1, tpu, 2048);
    k_tswiglu<<<8, 256>>>(tpu, tps);
    k_tpart<<<dim3(32, 2, 8), 128>>>(tps, w_t2, part, 1024, 4096);
    k_treduce<<<dim3(16, 2), 256>>>(part, b_t2, tp, 4096);

    // attention branch
    k_rmsnorm<<<4096, 256>>>(x, g1, tp, 0, 1024, h);
    k_tgemm<false, true><<<dim3(24, 32), 256, GEMM_SMEM>>>(h, w_qkv, b_qkv, nullptr, rtab, qkv, 3072, 1024);
    k_attn<<<dim3(32, 32), 128, ATTN_SMEM>>>(qkv, att);
    k_tgemm<true, false><<<dim3(8, 32), 256, GEMM_SMEM>>>(att, w_ao, b_ao, x, rtab, x1, 1024, 1024);

    // FFN branch
    k_rmsnorm<<<4096, 256>>>(x1, g2, tp, 2048, 3072, h);
    k_tgemm<false, false><<<dim3(64, 32), 256, GEMM_SMEM>>>(h, w_fc, b_fc, nullptr, rtab, u, 8192, 1024);
    k_swiglu<<<16384, 256>>>(u, sw);
    k_tgemm<true, false><<<dim3(8, 32), 256, GEMM_SMEM>>>(sw, w_fo, b_fo, x1, rtab, out, 1024, 4096);
}

// round 17
// speedup vs baseline: 1.5872x; 1.3275x over previous
#include <cuda_runtime.h>
#include <cuda_fp16.h>
#include <math.h>

// Problem constants: B=2, T=2048, D=1024, H=16, hd=64, M = B*T = 4096
#define MROWS 4096

// ---------------- scratch (device globals; no allocation allowed) ----------
__device__ float g_tpu [2 * 2048];       // time MLP hidden
__device__ float g_tps [2 * 1024];       // time MLP after swiglu
__device__ float g_tp  [2 * 4096];       // shift1|scale1|shift2|scale2
__device__ float g_part[8 * 2 * 4096];   // split-K partials for time MLP
__device__ float g_qkv [MROWS * 3072];   // qkv projections (rope fused)
__device__ float g_x1  [MROWS * 1024];   // x after attention residual
__device__ float g_u   [MROWS * 8192];   // ffn pre-activation
__device__ float2 g_ropetab[2048 * 32];  // (cos, sin) per (pos, pair)
// f16 operand buffers
__device__ __half g_h16  [MROWS * 1024]; // normed/modulated activations
__device__ __half g_att16[MROWS * 1024]; // attention output
__device__ __half g_sw16 [MROWS * 4096]; // ffn post-swiglu
__device__ __half g_w16  [16777216];     // wqkv|wao|wfc|wfo f16 arena
#define OQKV 0
#define OAO  3145728
#define OFC  4194304
#define OFO  12582912

// ---------------- PTX helpers ----------------------------------------------
__device__ __forceinline__ unsigned cvt_tf32(float f) {
    unsigned u;
    asm("cvt.rna.tf32.f32 %0, %1;" : "=r"(u) : "f"(f));
    return u;
}

__device__ __forceinline__ void mma_tf32(float* c, unsigned a0, unsigned a1,
                                         unsigned a2, unsigned a3,
                                         unsigned b0, unsigned b1) {
    asm volatile(
        "mma.sync.aligned.m16n8k8.row.col.f32.tf32.tf32.f32 "
        "{%0,%1,%2,%3}, {%4,%5,%6,%7}, {%8,%9}, {%0,%1,%2,%3};\n"
        : "+f"(c[0]), "+f"(c[1]), "+f"(c[2]), "+f"(c[3])
        : "r"(a0), "r"(a1), "r"(a2), "r"(a3), "r"(b0), "r"(b1));
}

__device__ __forceinline__ void mma_f16(float* c, unsigned a0, unsigned a1,
                                        unsigned a2, unsigned a3,
                                        unsigned b0, unsigned b1) {
    asm volatile(
        "mma.sync.aligned.m16n8k16.row.col.f32.f16.f16.f32 "
        "{%0,%1,%2,%3}, {%4,%5,%6,%7}, {%8,%9}, {%0,%1,%2,%3};\n"
        : "+f"(c[0]), "+f"(c[1]), "+f"(c[2]), "+f"(c[3])
        : "r"(a0), "r"(a1), "r"(a2), "r"(a3), "r"(b0), "r"(b1));
}

__device__ __forceinline__ void ldsm4(unsigned& r0, unsigned& r1,
                                      unsigned& r2, unsigned& r3, unsigned addr) {
    asm volatile("ldmatrix.sync.aligned.m8n8.x4.shared.b16 {%0,%1,%2,%3}, [%4];"
                 : "=r"(r0), "=r"(r1), "=r"(r2), "=r"(r3) : "r"(addr));
}

__device__ __forceinline__ void ldsm4t(unsigned& r0, unsigned& r1,
                                       unsigned& r2, unsigned& r3, unsigned addr) {
    asm volatile("ldmatrix.sync.aligned.m8n8.x4.trans.shared.b16 {%0,%1,%2,%3}, [%4];"
                 : "=r"(r0), "=r"(r1), "=r"(r2), "=r"(r3) : "r"(addr));
}

__device__ __forceinline__ void cp16(void* dst, const void* src) {
    unsigned ds = (unsigned)__cvta_generic_to_shared(dst);
    asm volatile("cp.async.cg.shared.global [%0], [%1], 16;\n" :: "r"(ds), "l"(src));
}
__device__ __forceinline__ void cp_commit() {
    asm volatile("cp.async.commit_group;\n");
}
template <int N>
__device__ __forceinline__ void cp_wait() {
    asm volatile("cp.async.wait_group %0;\n" :: "n"(N));
}

// ---------------- fp32 -> f16 conversion (weights) --------------------------
__global__ void k_cvtf16(const float4* __restrict__ in, __half2* __restrict__ out,
                         int n4) {
    int i = blockIdx.x * 256 + threadIdx.x;
    if (i >= n4) return;
    float4 v = in[i];
    out[2 * i]     = __floats2half2_rn(v.x, v.y);
    out[2 * i + 1] = __floats2half2_rn(v.z, v.w);
}

// ---------------- time-MLP: split-K partial GEMM + reduce -------------------
__global__ __launch_bounds__(128) void k_tpart(const float* __restrict__ in,
                                               const float* __restrict__ w,
                                               float* __restrict__ part,
                                               int K, int N) {
    int n = blockIdx.x * 128 + threadIdx.x;
    int b = blockIdx.y, s = blockIdx.z;
    const float* xr = in + b * K + s * 128;
    const float* wp = w + (size_t)(s * 128) * N + n;
    float acc = 0.f;
    #pragma unroll 8
    for (int k = 0; k < 128; ++k) acc += xr[k] * wp[(size_t)k * N];
    part[(s * 2 + b) * 4096 + n] = acc;
}

__global__ void k_treduce(const float* __restrict__ part,
                          const float* __restrict__ bias,
                          float* __restrict__ out, int N) {
    int n = blockIdx.x * 256 + threadIdx.x;
    int b = blockIdx.y;
    if (n >= N) return;
    float acc = bias[n];
    #pragma unroll
    for (int s = 0; s < 8; ++s) acc += part[(s * 2 + b) * 4096 + n];
    out[b * N + n] = acc;
}

__global__ void k_tswiglu(const float* __restrict__ u, float* __restrict__ s) {
    int i = blockIdx.x * 256 + threadIdx.x;  // 2048 total
    if (i >= 2048) return;
    int b = i >> 10, j = i & 1023;
    float a = u[b * 2048 + j];
    float g = u[b * 2048 + 1024 + j];
    s[b * 1024 + j] = a * (g / (1.f + expf(-g)));
}

// ---------------- rope cos/sin table ---------------------------------------
__global__ void k_ropetab(float2* __restrict__ tab) {
    int idx = blockIdx.x * 256 + threadIdx.x;   // 65536
    int t = idx >> 5, i = idx & 31;
    float inv = powf(10000.f, -(float)i * (1.f / 32.f));
    float sn, cs;
    sincosf((float)t * inv, &sn, &cs);
    tab[idx] = make_float2(cs, sn);
}

// ---------------- fused RMSNorm + adaLN modulation (f16 out) -----------------
__global__ __launch_bounds__(256) void k_rmsnorm(const float* __restrict__ x,
                                                 const float* __restrict__ g,
                                                 const float* __restrict__ tp,
                                                 int shift_off, int scale_off,
                                                 __half* __restrict__ out) {
    int row = blockIdx.x;          // 0..4095
    int b   = row >> 11;
    const float4* xr = (const float4*)(x + row * 1024);
    float4 v = xr[threadIdx.x];
    float ss = v.x * v.x + v.y * v.y + v.z * v.z + v.w * v.w;
    #pragma unroll
    for (int off = 16; off; off >>= 1) ss += __shfl_xor_sync(0xFFFFFFFFu, ss, off);
    __shared__ float wsum[8];
    __shared__ float stot;
    if ((threadIdx.x & 31) == 0) wsum[threadIdx.x >> 5] = ss;
    __syncthreads();
    if (threadIdx.x == 0) {
        float t = 0.f;
        #pragma unroll
        for (int i = 0; i < 8; ++i) t += wsum[i];
        stot = rsqrtf(t * (1.f / 1024.f) + 1.1920928955078125e-7f);
    }
    __syncthreads();
    float r = stot;
    int j = threadIdx.x * 4;
    const float* gg = g + j;
    const float* sc = tp + b * 4096 + scale_off + j;
    const float* sh = tp + b * 4096 + shift_off + j;
    float4 o;
    o.x = v.x * r * gg[0] * (1.f + sc[0]) + sh[0];
    o.y = v.y * r * gg[1] * (1.f + sc[1]) + sh[1];
    o.z = v.z * r * gg[2] * (1.f + sc[2]) + sh[2];
    o.w = v.w * r * gg[3] * (1.f + sc[3]) + sh[3];
    __half2 h0 = __floats2half2_rn(o.x, o.y);
    __half2 h1 = __floats2half2_rn(o.z, o.w);
    *(uint2*)(out + row * 1024 + j) =
        make_uint2(*(unsigned*)&h0, *(unsigned*)&h1);
}

// ---------------- native-f16 tensor-core GEMM, 3-stage cp.async -------------
// C[M,N] = A[M,K] @ B[K,N] + bias (+residual) (+rope on cols<2048).
// A, B in f16 gmem. Block 128x128, BK=16, 8 warps 2x4, warp tile 64x32,
// m16n8k16 f16, fp32 acc. Tiles loaded directly into ldmatrix-ready smem:
// A [m][48B] (16B pad), B [k][272B] (16B pad). Fragments via ldmatrix.
#define A16T(s, m) ((s) * 6144 + (m) * 48)
#define B16T(s, r) (18432 + (s) * 4352 + (r) * 272)
#define GEMM_SMEM (18432 + 3 * 4352)    // 31488 bytes

template <bool RES, bool ROPE>
__global__ __launch_bounds__(256) void k_tgemm(const __half* __restrict__ A,
                                               const __half* __restrict__ B,
                                               const float* __restrict__ bias,
                                               const float* __restrict__ res,
                                               const float2* __restrict__ rtab,
                                               float* __restrict__ C,
                                               int Nn, int Kn) {
    extern __shared__ __align__(16) char smem[];
    const unsigned smemu = (unsigned)__cvta_generic_to_shared(smem);

    const int tid  = threadIdx.x;
    const int lane = tid & 31;
    const int g    = lane >> 2;
    const int t    = lane & 3;
    const int warp = tid >> 5;
    const int wm   = (warp >> 2) * 64;
    const int wn   = (warp & 3) * 32;

    const int row0 = blockIdx.y * 128;
    const int col0 = blockIdx.x * 128;

    // load mapping: 2 cp16 per thread per tile
    const int a_row = tid >> 1;        // 0..127
    const int a_half = tid & 1;        // 8-half chunk
    const int b_row = tid >> 4;        // 0..15
    const int b_seg = tid & 15;        // 8-half chunk

    const __half* Ap = A + (size_t)(row0 + a_row) * Kn + a_half * 8;
    const __half* Bp = B + (size_t)b_row * Nn + col0 + b_seg * 8;

    // ldmatrix lane addressing
    const int a_lm = (lane & 7) + 8 * ((lane >> 3) & 1);   // m within 16
    const int a_lk = ((lane >> 4) & 1) * 16;               // k byte offset
    const int b_lk = ((lane >> 3) & 1) * 8 + (lane & 7);   // k row
    const int b_ln = ((lane >> 4) & 1) * 8;                // n within 16

    float acc[4][4][4];
    #pragma unroll
    for (int mi = 0; mi < 4; ++mi)
        #pragma unroll
        for (int ni = 0; ni < 4; ++ni)
            #pragma unroll
            for (int r = 0; r < 4; ++r) acc[mi][ni][r] = 0.f;

    const int tiles = Kn >> 4;

    #pragma unroll
    for (int s = 0; s < 2; ++s) {
        cp16(smem + A16T(s, a_row) + a_half * 16, Ap);
        cp16(smem + B16T(s, b_row) + b_seg * 16,  Bp);
        cp_commit();
        Ap += 16;
        Bp += (size_t)16 * Nn;
    }

    for (int i = 0; i < tiles; ++i) {
        const int buf = i % 3;
        cp_wait<1>();
        __syncthreads();
        if (i + 2 < tiles) {
            const int nb = (i + 2) % 3;
            cp16(smem + A16T(nb, a_row) + a_half * 16, Ap);
            cp16(smem + B16T(nb, b_row) + b_seg * 16,  Bp);
            Ap += 16;
            Bp += (size_t)16 * Nn;
        }
        cp_commit();   // always commit (keeps wait<1> semantics on the tail)

        unsigned af[4][4], bf[4][2];
        #pragma unroll
        for (int mi = 0; mi < 4; ++mi) {
            unsigned addr = smemu + A16T(buf, wm + mi * 16 + a_lm) + a_lk;
            ldsm4(af[mi][0], af[mi][1], af[mi][2], af[mi][3], addr);
        }
        #pragma unroll
        for (int bb = 0; bb < 2; ++bb) {
            unsigned addr = smemu + B16T(buf, b_lk) + (wn + bb * 16 + b_ln) * 2;
            unsigned r0, r1, r2, r3;
            ldsm4t(r0, r1, r2, r3, addr);
            bf[bb * 2][0]     = r0;  bf[bb * 2][1]     = r1;
            bf[bb * 2 + 1][0] = r2;  bf[bb * 2 + 1][1] = r3;
        }
        #pragma unroll
        for (int mi = 0; mi < 4; ++mi)
            #pragma unroll
            for (int ni = 0; ni < 4; ++ni)
                mma_f16(acc[mi][ni], af[mi][0], af[mi][1], af[mi][2], af[mi][3],
                        bf[ni][0], bf[ni][1]);
    }

    // epilogue: bias (+residual) (+rope), fp32 out
    #pragma unroll
    for (int mi = 0; mi < 4; ++mi) {
        int r_top = row0 + wm + mi * 16 + g;
        int r_bot = r_top + 8;
        #pragma unroll
        for (int ni = 0; ni < 4; ++ni) {
            int c = col0 + wn + ni * 8 + 2 * t;   // even column
            float bx = bias[c], by = bias[c + 1];
            float2 w0 = make_float2(acc[mi][ni][0] + bx, acc[mi][ni][1] + by);
            float2 w1 = make_float2(acc[mi][ni][2] + bx, acc[mi][ni][3] + by);
            if (RES) {
                float2 r0 = *(const float2*)(res + (size_t)r_top * Nn + c);
                float2 r1 = *(const float2*)(res + (size_t)r_bot * Nn + c);
                w0.x += r0.x; w0.y += r0.y;
                w1.x += r1.x; w1.y += r1.y;
            }
            if (ROPE && c < 2048) {            // q,k columns get rope
                int i = (c & 63) >> 1;
                float2 cs0 = rtab[(r_top & 2047) * 32 + i];
                float2 cs1 = rtab[(r_bot & 2047) * 32 + i];
                float a0 = w0.x, a1 = w0.y;
                w0.x = a0 * cs0.x - a1 * cs0.y;
                w0.y = a1 * cs0.x + a0 * cs0.y;
                a0 = w1.x; a1 = w1.y;
                w1.x = a0 * cs1.x - a1 * cs1.y;
                w1.y = a1 * cs1.x + a0 * cs1.y;
            }
            *(float2*)(C + (size_t)r_top * Nn + c) = w0;
            *(float2*)(C + (size_t)r_bot * Nn + c) = w1;
        }
    }
}

// ---------------- tensor-core flash attention, cp.async K/V pipeline --------
#define QP_STR 68
#define KS_STR 68
#define VS_STR 72
#define ATTN_SMEM (64 * (QP_STR + 2 * KS_STR + 2 * VS_STR) * 4)

__global__ __launch_bounds__(128) void k_attn(const float* __restrict__ qkv,
                                              __half* __restrict__ out) {
    extern __shared__ float sm[];
    float* QP = sm;                                   // 64*68
    float* Ks = sm + 64 * QP_STR;                     // 2 x 64*68
    float* Vs = sm + 64 * (QP_STR + 2 * KS_STR);      // 2 x 64*72

    const int tid  = threadIdx.x;
    const int lane = tid & 31;
    const int g    = lane >> 2;
    const int t    = lane & 3;
    const int warp = tid >> 5;
    const int m0   = warp * 16;

    const int qt = blockIdx.x, bh = blockIdx.y;
    const int b = bh >> 4, h = bh & 15;
    const int base_tok = b * 2048;

    const int ld_row = tid >> 4;
    const int ld_dc  = (tid & 15) << 2;

    #pragma unroll
    for (int rr = 0; rr < 8; ++rr) {
        int row = ld_row + rr * 8;
        int tok = base_tok + row;
        cp16(Ks + row * KS_STR + ld_dc, qkv + (size_t)tok * 3072 + 1024 + h * 64 + ld_dc);
        cp16(Vs + row * VS_STR + ld_dc, qkv + (size_t)tok * 3072 + 2048 + h * 64 + ld_dc);
    }
    cp_commit();

    #pragma unroll
    for (int f = tid; f < 1024; f += 128) {
        int row = f >> 4, dc = (f & 15) << 2;
        int tok = base_tok + qt * 64 + row;
        float4 q4 = *(const float4*)(qkv + (size_t)tok * 3072 + h * 64 + dc);
        uint4 u;
        u.x = cvt_tf32(q4.x * 0.125f); u.y = cvt_tf32(q4.y * 0.125f);
        u.z = cvt_tf32(q4.z * 0.125f); u.w = cvt_tf32(q4.w * 0.125f);
        *(uint4*)(QP + row * QP_STR + dc) = u;
    }
    __syncthreads();

    unsigned qa[8][4];
    #pragma unroll
    for (int ks = 0; ks < 8; ++ks) {
        const unsigned* q0 = (const unsigned*)(QP + (m0 + g) * QP_STR);
        const unsigned* q1 = (const unsigned*)(QP + (m0 + g + 8) * QP_STR);
        qa[ks][0] = q0[ks * 8 + t];
        qa[ks][1] = q1[ks * 8 + t];
        qa[ks][2] = q0[ks * 8 + t + 4];
        qa[ks][3] = q1[ks * 8 + t + 4];
    }

    float o[8][4];
    #pragma unroll
    for (int j = 0; j < 8; ++j)
        #pragma unroll
        for (int r = 0; r < 4; ++r) o[j][r] = 0.f;
    float M1 = -INFINITY, M2 = -INFINITY, L1 = 0.f, L2 = 0.f;

    for (int kt = 0; kt < 32; ++kt) {
        const int buf = kt & 1;
        float* Kb = Ks + buf * 64 * KS_STR;
        float* Vb = Vs + buf * 64 * VS_STR;

        __syncthreads();
        if (kt + 1 < 32) {
            float* Kn = Ks + (buf ^ 1) * 64 * KS_STR;
            float* Vn = Vs + (buf ^ 1) * 64 * VS_STR;
            #pragma unroll
            for (int rr = 0; rr < 8; ++rr) {
                int row = ld_row + rr * 8;
                int tok = base_tok + (kt + 1) * 64 + row;
                cp16(Kn + row * KS_STR + ld_dc, qkv + (size_t)tok * 3072 + 1024 + h * 64 + ld_dc);
                cp16(Vn + row * VS_STR + ld_dc, qkv + (size_t)tok * 3072 + 2048 + h * 64 + ld_dc);
            }
        }
        cp_commit();
        cp_wait<1>();
        __syncthreads();

        float s[8][4];
        #pragma unroll
        for (int j = 0; j < 8; ++j)
            #pragma unroll
            for (int r = 0; r < 4; ++r) s[j][r] = 0.f;

        #pragma unroll
        for (int ks = 0; ks < 8; ++ks) {
            unsigned kb[8][2];
            #pragma unroll
            for (int j = 0; j < 8; ++j) {
                const unsigned* kr = (const unsigned*)(Kb + (j * 8 + g) * KS_STR);
                kb[j][0] = kr[ks * 8 + t]     + 0x1000u;
                kb[j][1] = kr[ks * 8 + t + 4] + 0x1000u;
            }
            #pragma unroll
            for (int j = 0; j < 8; ++j)
                mma_tf32(s[j], qa[ks][0], qa[ks][1], qa[ks][2], qa[ks][3],
                         kb[j][0], kb[j][1]);
        }

        float mx1 = -INFINITY, mx2 = -INFINITY;
        #pragma unroll
        for (int j = 0; j < 8; ++j) {
            mx1 = fmaxf(mx1, fmaxf(s[j][0], s[j][1]));
            mx2 = fmaxf(mx2, fmaxf(s[j][2], s[j][3]));
        }
        mx1 = fmaxf(mx1, __shfl_xor_sync(0xFFFFFFFFu, mx1, 1));
        mx1 = fmaxf(mx1, __shfl_xor_sync(0xFFFFFFFFu, mx1, 2));
        mx2 = fmaxf(mx2, __shfl_xor_sync(0xFFFFFFFFu, mx2, 1));
        mx2 = fmaxf(mx2, __shfl_xor_sync(0xFFFFFFFFu, mx2, 2));
        float mn1 = fmaxf(M1, mx1), mn2 = fmaxf(M2, mx2);
        float cr1 = __expf(M1 - mn1), cr2 = __expf(M2 - mn2);
        float l1 = 0.f, l2 = 0.f;
        #pragma unroll
        for (int j = 0; j < 8; ++j) {
            s[j][0] = __expf(s[j][0] - mn1);
            s[j][1] = __expf(s[j][1] - mn1);
            s[j][2] = __expf(s[j][2] - mn2);
            s[j][3] = __expf(s[j][3] - mn2);
            l1 += s[j][0] + s[j][1];
            l2 += s[j][2] + s[j][3];
        }
        l1 += __shfl_xor_sync(0xFFFFFFFFu, l1, 1);
        l1 += __shfl_xor_sync(0xFFFFFFFFu, l1, 2);
        l2 += __shfl_xor_sync(0xFFFFFFFFu, l2, 1);
        l2 += __shfl_xor_sync(0xFFFFFFFFu, l2, 2);
        L1 = L1 * cr1 + l1;  M1 = mn1;
        L2 = L2 * cr2 + l2;  M2 = mn2;
        #pragma unroll
        for (int j = 0; j < 8; ++j) {
            o[j][0] *= cr1; o[j][1] *= cr1;
            o[j][2] *= cr2; o[j][3] *= cr2;
        }

        #pragma unroll
        for (int j = 0; j < 8; ++j) {
            unsigned* p0 = (unsigned*)(QP + (m0 + g) * QP_STR);
            unsigned* p1 = (unsigned*)(QP + (m0 + g + 8) * QP_STR);
            p0[j * 8 + 2 * t]     = cvt_tf32(s[j][0]);
            p0[j * 8 + 2 * t + 1] = cvt_tf32(s[j][1]);
            p1[j * 8 + 2 * t]     = cvt_tf32(s[j][2]);
            p1[j * 8 + 2 * t + 1] = cvt_tf32(s[j][3]);
        }
        __syncwarp();

        #pragma unroll
        for (int ks = 0; ks < 8; ++ks) {
            const unsigned* p0 = (const unsigned*)(QP + (m0 + g) * QP_STR);
            const unsigned* p1 = (const unsigned*)(QP + (m0 + g + 8) * QP_STR);
            unsigned pa0 = p0[ks * 8 + t];
            unsigned pa1 = p1[ks * 8 + t];
            unsigned pa2 = p0[ks * 8 + t + 4];
            unsigned pa3 = p1[ks * 8 + t + 4];
            #pragma unroll
            for (int j = 0; j < 8; ++j) {
                const unsigned* vr  = (const unsigned*)(Vb + (ks * 8 + t) * VS_STR);
                const unsigned* vr4 = (const unsigned*)(Vb + (ks * 8 + t + 4) * VS_STR);
                unsigned vb0 = vr[j * 8 + g]  + 0x1000u;
                unsigned vb1 = vr4[j * 8 + g] + 0x1000u;
                mma_tf32(o[j], pa0, pa1, pa2, pa3, vb0, vb1);
            }
        }
    }

    float r1 = 1.f / L1, r2 = 1.f / L2;
    int row1 = base_tok + qt * 64 + m0 + g;
    int row2 = row1 + 8;
    #pragma unroll
    for (int j = 0; j < 8; ++j) {
        int c = h * 64 + j * 8 + 2 * t;
        __half2 h0 = __floats2half2_rn(o[j][0] * r1, o[j][1] * r1);
        __half2 h1 = __floats2half2_rn(o[j][2] * r2, o[j][3] * r2);
        *(__half2*)(out + (size_t)row1 * 1024 + c) = h0;
        *(__half2*)(out + (size_t)row2 * 1024 + c) = h1;
    }
}

// ---------------- SwiGLU for FFN (f16 out) ----------------------------------
__global__ void k_swiglu(const float* __restrict__ u, __half* __restrict__ s) {
    int idx = blockIdx.x * 256 + threadIdx.x;
    int m = idx >> 10, c4 = (idx & 1023) << 2;
    float4 a = *(const float4*)(u + (size_t)m * 8192 + c4);
    float4 g = *(const float4*)(u + (size_t)m * 8192 + 4096 + c4);
    float4 o;
    o.x = a.x * (g.x / (1.f + __expf(-g.x)));
    o.y = a.y * (g.y / (1.f + __expf(-g.y)));
    o.z = a.z * (g.z / (1.f + __expf(-g.z)));
    o.w = a.w * (g.w / (1.f + __expf(-g.w)));
    __half2 h0 = __floats2half2_rn(o.x, o.y);
    __half2 h1 = __floats2half2_rn(o.z, o.w);
    *(uint2*)(s + (size_t)m * 4096 + c4) =
        make_uint2(*(unsigned*)&h0, *(unsigned*)&h1);
}

// ---------------- launcher --------------------------------------------------
extern "C" void kernel_launch(void* const* d_in, const int* in_sizes, int n_in,
                              void* d_out, int out_size) {
    const float* x     = (const float*)d_in[0];
    const float* temb  = (const float*)d_in[1];
    const float* g1    = (const float*)d_in[2];
    const float* g2    = (const float*)d_in[3];
    const float* w_qkv = (const float*)d_in[4];
    const float* b_qkv = (const float*)d_in[5];
    const float* w_ao  = (const float*)d_in[6];
    const float* b_ao  = (const float*)d_in[7];
    const float* w_fc  = (const float*)d_in[8];
    const float* b_fc  = (const float*)d_in[9];
    const float* w_fo  = (const float*)d_in[10];
    const float* b_fo  = (const float*)d_in[11];
    const float* w_t1  = (const float*)d_in[12];
    const float* b_t1  = (const float*)d_in[13];
    const float* w_t2  = (const float*)d_in[14];
    const float* b_t2  = (const float*)d_in[15];
    float* out = (float*)d_out;

    float *tpu, *tps, *tp, *part, *qkv, *x1, *u;
    __half *h16, *att16, *sw16, *w16;
    float2* rtab;
    cudaGetSymbolAddress((void**)&tpu,   g_tpu);
    cudaGetSymbolAddress((void**)&tps,   g_tps);
    cudaGetSymbolAddress((void**)&tp,    g_tp);
    cudaGetSymbolAddress((void**)&part,  g_part);
    cudaGetSymbolAddress((void**)&qkv,   g_qkv);
    cudaGetSymbolAddress((void**)&x1,    g_x1);
    cudaGetSymbolAddress((void**)&u,     g_u);
    cudaGetSymbolAddress((void**)&h16,   g_h16);
    cudaGetSymbolAddress((void**)&att16, g_att16);
    cudaGetSymbolAddress((void**)&sw16,  g_sw16);
    cudaGetSymbolAddress((void**)&w16,   g_w16);
    cudaGetSymbolAddress((void**)&rtab,  g_ropetab);

    cudaFuncSetAttribute(k_attn, cudaFuncAttributeMaxDynamicSharedMemorySize, ATTN_SMEM);
    cudaFuncSetAttribute(k_tgemm<false, true>,  cudaFuncAttributeMaxDynamicSharedMemorySize, GEMM_SMEM);
    cudaFuncSetAttribute(k_tgemm<true, false>,  cudaFuncAttributeMaxDynamicSharedMemorySize, GEMM_SMEM);
    cudaFuncSetAttribute(k_tgemm<false, false>, cudaFuncAttributeMaxDynamicSharedMemorySize, GEMM_SMEM);

    // weight conversions (f16 arena) + rope table
    k_cvtf16<<<3072, 256>>>((const float4*)w_qkv, (__half2*)(w16 + OQKV), 786432);
    k_cvtf16<<<1024, 256>>>((const float4*)w_ao,  (__half2*)(w16 + OAO),  262144);
    k_cvtf16<<<8192, 256>>>((const float4*)w_fc,  (__half2*)(w16 + OFC),  2097152);
    k_cvtf16<<<4096, 256>>>((const float4*)w_fo,  (__half2*)(w16 + OFO),  1048576);
    k_ropetab<<<256, 256>>>(rtab);

    // time-conditioning MLP (split-K, deterministic)
    k_tpart<<<dim3(16, 2, 8), 128>>>(temb, w_t1, part, 1024, 2048);
    k_treduce<<<dim3(8, 2), 256>>>(part, b_t1, tpu, 2048);
    k_tswiglu<<<8, 256>>>(tpu, tps);
    k_tpart<<<dim3(32, 2, 8), 128>>>(tps, w_t2, part, 1024, 4096);
    k_treduce<<<dim3(16, 2), 256>>>(part, b_t2, tp, 4096);

    // attention branch
    k_rmsnorm<<<4096, 256>>>(x, g1, tp, 0, 1024, h16);
    k_tgemm<false, true><<<dim3(24, 32), 256, GEMM_SMEM>>>(h16, w16 + OQKV, b_qkv, nullptr, rtab, qkv, 3072, 1024);
    k_attn<<<dim3(32, 32), 128, ATTN_SMEM>>>(qkv, att16);
    k_tgemm<true, false><<<dim3(8, 32), 256, GEMM_SMEM>>>(att16, w16 + OAO, b_ao, x, rtab, x1, 1024, 1024);

    // FFN branch
    k_rmsnorm<<<4096, 256>>>(x1, g2, tp, 2048, 3072, h16);
    k_tgemm<false, false><<<dim3(64, 32), 256, GEMM_SMEM>>>(h16, w16 + OFC, b_fc, nullptr, rtab, u, 8192, 1024);
    k_swiglu<<<16384, 256>>>(u, sw16);
    k_tgemm<true, false><<<dim3(8, 32), 256, GEMM_SMEM>>>(sw16, w16 + OFO, b_fo, x1, rtab, out, 1024, 4096);
}